// round 1
// baseline (speedup 1.0000x reference)
#include <cuda_runtime.h>
#include <math.h>

// Problem constants
#define NN   307
#define TT   12
#define BB   128
#define DIN  2
#define DOUT 64
#define DE   10

#define BND   (BB*NN*DOUT)        // 2,514,944 elements  (one [B,N,DOUT] tensor)
#define CURSZ (BB*TT*NN*DOUT)     // 30,179,328 elements (the [B,T,N,DOUT] output)

// ---------------------------------------------------------------------------
// Device scratch (static __device__ arrays: the sanctioned no-alloc workaround)
// ---------------------------------------------------------------------------
__device__ float g_Wg0[NN*132*128];   // layer0 gate  weights  [n][kk=132][128]
__device__ float g_Wu0[NN*132*64];    // layer0 cand  weights  [n][132][64]
__device__ float g_Wg1[NN*256*128];   // layer1 gate  weights  [n][256][128]
__device__ float g_Wu1[NN*256*64];    // layer1 cand  weights  [n][256][64]
__device__ float g_bg0[NN*128];
__device__ float g_bu0[NN*64];
__device__ float g_bg1[NN*128];
__device__ float g_bu1[NN*64];

__device__ float g_h  [BND];          // hidden state [B,N,64]
__device__ float g_zh [BND];          // z*h          [B,N,64]
__device__ float g_r  [BND];          // r gate       [B,N,64]
__device__ float g_Gx2[BB*NN*DIN];    // adj @ x (layer0, 2 ch)  [B,N,2]
__device__ float g_Gx [BND];          // adj @ x (layer1, 64 ch) [B,N,64]
__device__ float g_Gh [BND];          // adj @ h
__device__ float g_Gzh[BND];          // adj @ (z*h)
__device__ float g_seq0[CURSZ];       // layer0 output sequence [B,T,N,64]

__device__ __forceinline__ float sigm(float v) { return 1.0f / (1.0f + expf(-v)); }

// ---------------------------------------------------------------------------
// Precompute per-node weights: out[n, j] = sum_d E[n,d] * pool[d, j]
// which selects destination global. S = elements per node.
// ---------------------------------------------------------------------------
__global__ void prep_weights(const float* __restrict__ E,
                             const float* __restrict__ pool,
                             int which, int S) {
    long idx = (long)blockIdx.x * blockDim.x + threadIdx.x;
    long total = (long)NN * S;
    if (idx >= total) return;
    int n = (int)(idx / S);
    long j = idx - (long)n * S;
    float acc = 0.0f;
#pragma unroll
    for (int d = 0; d < DE; d++)
        acc += E[n*DE + d] * pool[(long)d*S + j];
    float* out;
    switch (which) {
        case 0: out = g_Wg0; break;
        case 1: out = g_Wu0; break;
        case 2: out = g_Wg1; break;
        case 3: out = g_Wu1; break;
        case 4: out = g_bg0; break;
        case 5: out = g_bu0; break;
        case 6: out = g_bg1; break;
        default: out = g_bu1; break;
    }
    out[idx] = acc;
}

// h <- init_state[l]
__global__ void init_h(const float* __restrict__ init, int l) {
    int i = blockIdx.x * blockDim.x + threadIdx.x;
    if (i < BND) g_h[i] = init[(long)l*BND + i];
}

// ---------------------------------------------------------------------------
// Graph propagation, 2-channel (layer0 x part): Gx2[b,n,c] = sum_m adj[n,m] x[b,t,m,c]
// ---------------------------------------------------------------------------
__global__ void graph_x2(const float* __restrict__ adj,
                         const float* __restrict__ x, int t) {
    int idx = blockIdx.x * blockDim.x + threadIdx.x;
    if (idx >= BB*NN*DIN) return;
    int c = idx & 1;
    int n = (idx >> 1) % NN;
    int b = idx / (NN*DIN);
    const float* xr = x + ((long)(b*TT + t))*NN*DIN + c;
    const float* ar = adj + (long)n*NN;
    float acc = 0.0f;
    for (int m = 0; m < NN; m++)
        acc += ar[m] * xr[m*DIN];
    g_Gx2[idx] = acc;
}

// ---------------------------------------------------------------------------
// Graph propagation, 64-channel: dst[b,n,c] = sum_m adj[n,m] src(b,m,c)
// srcsel: 0=g_h, 1=g_zh, 2=g_seq0 at time t.  dstsel: 0=g_Gh, 1=g_Gzh, 2=g_Gx
// Tiled GEMM per batch: block = (64 nodes x 64 channels), grid (5, B).
// ---------------------------------------------------------------------------
__global__ void __launch_bounds__(256) graph64(const float* __restrict__ adj,
                                               int srcsel, int t, int dstsel) {
    const float* src;
    long bstride;
    if (srcsel == 0)      { src = g_h;   bstride = (long)NN*DOUT; }
    else if (srcsel == 1) { src = g_zh;  bstride = (long)NN*DOUT; }
    else                  { src = g_seq0 + (long)t*NN*DOUT; bstride = (long)TT*NN*DOUT; }
    float* dst = (dstsel == 0) ? g_Gh : ((dstsel == 1) ? g_Gzh : g_Gx);

    int b  = blockIdx.y;
    int n0 = blockIdx.x * 64;
    int tid = threadIdx.x;
    int tx = tid & 15;    // channel group (4 ch each)
    int ty = tid >> 4;    // node group    (4 nodes each)

    __shared__ float adjs[32][65];   // [m][n], padded for conflict-free store
    __shared__ float srcs[32][64];   // [m][c]

    float acc[4][4] = {};
    const float* sb = src + (long)b * bstride;

    for (int m0 = 0; m0 < NN; m0 += 32) {
#pragma unroll
        for (int j = 0; j < 8; j++) {          // adj tile 64x32
            int lin = tid + j*256;
            int nl = lin >> 5, ml = lin & 31;
            int n = n0 + nl, m = m0 + ml;
            adjs[ml][nl] = (n < NN && m < NN) ? adj[(long)n*NN + m] : 0.0f;
        }
#pragma unroll
        for (int j = 0; j < 8; j++) {          // src tile 32x64
            int lin = tid + j*256;
            int ml = lin >> 6, c = lin & 63;
            int m = m0 + ml;
            srcs[ml][c] = (m < NN) ? sb[(long)m*DOUT + c] : 0.0f;
        }
        __syncthreads();
#pragma unroll
        for (int ml = 0; ml < 32; ml++) {
            float a0 = adjs[ml][ty*4+0];
            float a1 = adjs[ml][ty*4+1];
            float a2 = adjs[ml][ty*4+2];
            float a3 = adjs[ml][ty*4+3];
            float4 s = *(const float4*)&srcs[ml][tx*4];
            acc[0][0] += a0*s.x; acc[0][1] += a0*s.y; acc[0][2] += a0*s.z; acc[0][3] += a0*s.w;
            acc[1][0] += a1*s.x; acc[1][1] += a1*s.y; acc[1][2] += a1*s.z; acc[1][3] += a1*s.w;
            acc[2][0] += a2*s.x; acc[2][1] += a2*s.y; acc[2][2] += a2*s.z; acc[2][3] += a2*s.w;
            acc[3][0] += a3*s.x; acc[3][1] += a3*s.y; acc[3][2] += a3*s.z; acc[3][3] += a3*s.w;
        }
        __syncthreads();
    }
#pragma unroll
    for (int i = 0; i < 4; i++) {
        int n = n0 + ty*4 + i;
        if (n < NN) {
            float4 v = make_float4(acc[i][0], acc[i][1], acc[i][2], acc[i][3]);
            *(float4*)&dst[((long)b*NN + n)*DOUT + tx*4] = v;
        }
    }
}

// ---------------------------------------------------------------------------
// Per-node GEMM with fused GRU epilogue.
//   A[b, kk] (kk in [0, KD)) = [ x(CIN) | h_or_zh(64) | Gx(CIN) | Gh_or_Gzh(64) ]
//   out[b, og] = act( A @ W[n] + bias[n] )
// MODE 0 (gate GCN):   CO=128, grid.y=2.  gy=0 -> z half -> writes g_zh = z*h
//                                          gy=1 -> r half -> writes g_r
// MODE 1 (cand GCN):   CO=64.  hc=tanh(.); h' = r*h + (1-r)*hc -> g_h, seq, last.
// Block: 128(b) x 64(o) output tile, 256 threads, 8x4 register tile, K-tile 32.
// ---------------------------------------------------------------------------
template<int CIN, int MODE>
__global__ void __launch_bounds__(256) gemm_k(const float* __restrict__ xext, int t,
                                              float* __restrict__ curOut,
                                              float* __restrict__ lastOut) {
    constexpr int KD  = 2*CIN + 2*DOUT;        // 132 (layer0) or 256 (layer1)
    constexpr int CO  = MODE ? 64 : 128;
    constexpr int NKT = (KD + 31) / 32;        // 5 or 8

    const float* W    = (CIN == 2) ? (MODE ? g_Wu0 : g_Wg0) : (MODE ? g_Wu1 : g_Wg1);
    const float* bias = (CIN == 2) ? (MODE ? g_bu0 : g_bg0) : (MODE ? g_bu1 : g_bg1);
    const float* hsrc = MODE ? g_zh : g_h;
    const float* Gxp  = (CIN == 2) ? g_Gx2 : g_Gx;
    const float* Ghp  = MODE ? g_Gzh : g_Gh;

    const float* xbase;
    long xbs;
    if (CIN == 2) { xbase = xext  + (long)t*NN*DIN;  xbs = (long)TT*NN*DIN;  }
    else          { xbase = g_seq0 + (long)t*NN*DOUT; xbs = (long)TT*NN*DOUT; }

    int n  = blockIdx.x;
    int gy = blockIdx.y;
    int tid = threadIdx.x;
    int tx = tid & 15;    // out group (4 cols each)
    int ty = tid >> 4;    // batch group (8 rows each)

    __shared__ float As[32][132];   // [kk][b], padded
    __shared__ float Ws[32][64];    // [kk][o]

    float acc[8][4] = {};

    for (int kt = 0; kt < NKT; kt++) {
        int k0 = kt*32;
        // A tile: 128 b x 32 kk (gathered from 4 sources)
#pragma unroll
        for (int j = 0; j < 16; j++) {
            int lin = tid + j*256;
            int b   = lin >> 5;
            int kkl = lin & 31;
            int kk  = k0 + kkl;
            float v = 0.0f;
            if (kk < CIN)
                v = xbase[(long)b*xbs + (long)n*CIN + kk];
            else if (kk < CIN + 64)
                v = hsrc[((long)b*NN + n)*64 + (kk - CIN)];
            else if (kk < 2*CIN + 64)
                v = Gxp[((long)b*NN + n)*CIN + (kk - (CIN + 64))];
            else if (kk < KD)
                v = Ghp[((long)b*NN + n)*64 + (kk - (2*CIN + 64))];
            As[kkl][b] = v;
        }
        // W tile: 32 kk x 64 o
#pragma unroll
        for (int j = 0; j < 8; j++) {
            int lin = tid + j*256;
            int row = lin >> 6;
            int col = lin & 63;
            int kk  = k0 + row;
            Ws[row][col] = (kk < KD)
                ? W[(long)n*KD*CO + (long)kk*CO + gy*64 + col] : 0.0f;
        }
        __syncthreads();
#pragma unroll
        for (int kk = 0; kk < 32; kk++) {
            const float* arow = &As[kk][ty*8];
            float4 a0 = *(const float4*)(arow);
            float4 a1 = *(const float4*)(arow + 4);
            float4 w  = *(const float4*)&Ws[kk][tx*4];
            float av[8] = {a0.x, a0.y, a0.z, a0.w, a1.x, a1.y, a1.z, a1.w};
#pragma unroll
            for (int i = 0; i < 8; i++) {
                acc[i][0] += av[i]*w.x;
                acc[i][1] += av[i]*w.y;
                acc[i][2] += av[i]*w.z;
                acc[i][3] += av[i]*w.w;
            }
        }
        __syncthreads();
    }

    // Epilogue
    int og0 = gy*64 + tx*4;
    float b0 = bias[n*CO + og0 + 0];
    float b1 = bias[n*CO + og0 + 1];
    float b2 = bias[n*CO + og0 + 2];
    float b3 = bias[n*CO + og0 + 3];

#pragma unroll
    for (int i = 0; i < 8; i++) {
        int b = ty*8 + i;
        long base = ((long)b*NN + n)*DOUT + tx*4;
        if (MODE == 0) {
            float s0 = sigm(acc[i][0] + b0);
            float s1 = sigm(acc[i][1] + b1);
            float s2 = sigm(acc[i][2] + b2);
            float s3 = sigm(acc[i][3] + b3);
            if (gy == 0) {                       // z half -> z*h
                float4 hv = *(const float4*)&g_h[base];
                float4 o = make_float4(s0*hv.x, s1*hv.y, s2*hv.z, s3*hv.w);
                *(float4*)&g_zh[base] = o;
            } else {                             // r half
                *(float4*)&g_r[base] = make_float4(s0, s1, s2, s3);
            }
        } else {
            float hc0 = tanhf(acc[i][0] + b0);
            float hc1 = tanhf(acc[i][1] + b1);
            float hc2 = tanhf(acc[i][2] + b2);
            float hc3 = tanhf(acc[i][3] + b3);
            float4 rv = *(const float4*)&g_r[base];
            float4 hv = *(const float4*)&g_h[base];
            float4 o;
            o.x = rv.x*hv.x + (1.0f - rv.x)*hc0;
            o.y = rv.y*hv.y + (1.0f - rv.y)*hc1;
            o.z = rv.z*hv.z + (1.0f - rv.z)*hc2;
            o.w = rv.w*hv.w + (1.0f - rv.w)*hc3;
            *(float4*)&g_h[base] = o;
            float* seq = (CIN == 2) ? g_seq0 : curOut;
            *(float4*)&seq[((long)(b*TT + t))*NN*DOUT + (long)n*DOUT + tx*4] = o;
            if (lastOut)
                *(float4*)&lastOut[base] = o;
        }
    }
}

// ---------------------------------------------------------------------------
// Host driver — graph-capturable (kernel launches only, default stream)
// ---------------------------------------------------------------------------
extern "C" void kernel_launch(void* const* d_in, const int* in_sizes, int n_in,
                              void* d_out, int out_size) {
    const float* x    = (const float*)d_in[0];
    const float* init = (const float*)d_in[1];
    const float* E    = (const float*)d_in[2];
    const float* adj  = (const float*)d_in[3];
    const float* wg0  = (const float*)d_in[4];
    const float* bg0  = (const float*)d_in[5];
    const float* wu0  = (const float*)d_in[6];
    const float* bu0  = (const float*)d_in[7];
    const float* wg1  = (const float*)d_in[8];
    const float* bg1  = (const float*)d_in[9];
    const float* wu1  = (const float*)d_in[10];
    const float* bu1  = (const float*)d_in[11];

    float* out      = (float*)d_out;
    float* lastBase = out + (long)CURSZ;   // last_states [L,B,N,DOUT] after current

    auto gl = [](long n) { return (unsigned)((n + 255) / 256); };

    // Precompute per-node weights/biases (time-invariant)
    prep_weights<<<gl((long)NN*132*128), 256>>>(E, wg0, 0, 132*128);
    prep_weights<<<gl((long)NN*132*64),  256>>>(E, wu0, 1, 132*64);
    prep_weights<<<gl((long)NN*256*128), 256>>>(E, wg1, 2, 256*128);
    prep_weights<<<gl((long)NN*256*64),  256>>>(E, wu1, 3, 256*64);
    prep_weights<<<gl((long)NN*128),     256>>>(E, bg0, 4, 128);
    prep_weights<<<gl((long)NN*64),      256>>>(E, bu0, 5, 64);
    prep_weights<<<gl((long)NN*128),     256>>>(E, bg1, 6, 128);
    prep_weights<<<gl((long)NN*64),      256>>>(E, bu1, 7, 64);

    dim3 gGrid(5, BB);

    // ---- layer 0 ----
    init_h<<<gl(BND), 256>>>(init, 0);
    for (int t = 0; t < TT; t++) {
        graph_x2<<<gl((long)BB*NN*DIN), 256>>>(adj, x, t);          // Gx2 = adj @ x_t
        graph64<<<gGrid, 256>>>(adj, 0, t, 0);                      // Gh  = adj @ h
        gemm_k<2,0><<<dim3(NN,2), 256>>>(x, t, nullptr, nullptr);   // z*h, r
        graph64<<<gGrid, 256>>>(adj, 1, t, 1);                      // Gzh = adj @ (z*h)
        gemm_k<2,1><<<dim3(NN,1), 256>>>(x, t, nullptr,
                        (t == TT-1) ? lastBase : nullptr);          // h', seq0
    }
    // ---- layer 1 ----
    init_h<<<gl(BND), 256>>>(init, 1);
    for (int t = 0; t < TT; t++) {
        graph64<<<gGrid, 256>>>(adj, 2, t, 2);                      // Gx  = adj @ seq0_t
        graph64<<<gGrid, 256>>>(adj, 0, t, 0);                      // Gh
        gemm_k<64,0><<<dim3(NN,2), 256>>>(nullptr, t, nullptr, nullptr);
        graph64<<<gGrid, 256>>>(adj, 1, t, 1);                      // Gzh
        gemm_k<64,1><<<dim3(NN,1), 256>>>(nullptr, t, out,
                        (t == TT-1) ? lastBase + BND : nullptr);    // h', current
    }
}

// round 2
// speedup vs baseline: 1.0537x; 1.0537x over previous
#include <cuda_runtime.h>
#include <math.h>

// Problem constants
#define NN   307
#define TT   12
#define BB   128
#define DIN  2
#define DOUT 64
#define DE   10

#define BND   (BB*NN*DOUT)        // 2,514,944
#define CURSZ (BB*TT*NN*DOUT)     // 30,179,328
#define BT    (BB*TT)             // 1536

// ---------------------------------------------------------------------------
// Device scratch
// ---------------------------------------------------------------------------
__device__ float g_Wg0[NN*132*128];
__device__ float g_Wu0[NN*132*64];
__device__ float g_Wg1[NN*256*128];
__device__ float g_Wu1[NN*256*64];
__device__ float g_bg0[NN*128];
__device__ float g_bu0[NN*64];
__device__ float g_bg1[NN*128];
__device__ float g_bu1[NN*64];

__device__ float g_h    [BND];        // hidden state [B,N,64]
__device__ float g_zh   [BND];        // z*h
__device__ float g_r    [BND];        // r gate
__device__ float g_Gx2  [BT*NN*DIN];  // adj @ x  (layer0, all t)  [B,T,N,2]
__device__ float g_Gxall[CURSZ];      // adj @ seq0 (layer1, all t) [B,T,N,64]
__device__ float g_Gh   [BND];        // adj @ h
__device__ float g_Gzh  [BND];        // adj @ (z*h)
__device__ float g_seq0 [CURSZ];      // layer0 output sequence [B,T,N,64]

__device__ __forceinline__ float sigm(float v) { return 1.0f / (1.0f + expf(-v)); }

// packed fp32x2 helpers (bit-identical to scalar fp32 FMA, 2x FMA pipe rate)
__device__ __forceinline__ unsigned long long pk2(float x, float y) {
    unsigned long long r;
    asm("mov.b64 %0, {%1, %2};" : "=l"(r) : "f"(x), "f"(y));
    return r;
}
__device__ __forceinline__ unsigned long long ffma2(unsigned long long a,
                                                    unsigned long long b,
                                                    unsigned long long c) {
    unsigned long long d;
    asm("fma.rn.f32x2 %0, %1, %2, %3;" : "=l"(d) : "l"(a), "l"(b), "l"(c));
    return d;
}
__device__ __forceinline__ void unpk2(unsigned long long v, float& lo, float& hi) {
    asm("mov.b64 {%0, %1}, %2;" : "=f"(lo), "=f"(hi) : "l"(v));
}

// ---------------------------------------------------------------------------
// Single-launch weight precompute (all 8 pools)
// ---------------------------------------------------------------------------
#define S_WG0 (132*128)
#define S_WU0 (132*64)
#define S_WG1 (256*128)
#define S_WU1 (256*64)
#define C0 ((long)NN*S_WG0)
#define C1 (C0 + (long)NN*S_WU0)
#define C2 (C1 + (long)NN*S_WG1)
#define C3 (C2 + (long)NN*S_WU1)
#define C4 (C3 + (long)NN*128)
#define C5 (C4 + (long)NN*64)
#define C6 (C5 + (long)NN*128)
#define C7 (C6 + (long)NN*64)

__global__ void prep_all(const float* __restrict__ E,
                         const float* __restrict__ wg0, const float* __restrict__ wu0,
                         const float* __restrict__ wg1, const float* __restrict__ wu1,
                         const float* __restrict__ bg0, const float* __restrict__ bu0,
                         const float* __restrict__ bg1, const float* __restrict__ bu1) {
    long idx = (long)blockIdx.x * blockDim.x + threadIdx.x;
    if (idx >= C7) return;
    const float* pool; float* out; long loc; int S;
    if      (idx < C0) { pool = wg0; out = g_Wg0; loc = idx;      S = S_WG0; }
    else if (idx < C1) { pool = wu0; out = g_Wu0; loc = idx - C0; S = S_WU0; }
    else if (idx < C2) { pool = wg1; out = g_Wg1; loc = idx - C1; S = S_WG1; }
    else if (idx < C3) { pool = wu1; out = g_Wu1; loc = idx - C2; S = S_WU1; }
    else if (idx < C4) { pool = bg0; out = g_bg0; loc = idx - C3; S = 128;   }
    else if (idx < C5) { pool = bu0; out = g_bu0; loc = idx - C4; S = 64;    }
    else if (idx < C6) { pool = bg1; out = g_bg1; loc = idx - C5; S = 128;   }
    else               { pool = bu1; out = g_bu1; loc = idx - C6; S = 64;    }
    int n = (int)(loc / S);
    long j = loc - (long)n * S;
    float acc = 0.0f;
#pragma unroll
    for (int d = 0; d < DE; d++)
        acc += E[n*DE + d] * pool[(long)d*S + j];
    out[loc] = acc;
}

__global__ void init_h(const float* __restrict__ init, int l) {
    int i = blockIdx.x * blockDim.x + threadIdx.x;
    if (i < BND) g_h[i] = init[(long)l*BND + i];
}

// ---------------------------------------------------------------------------
// adj @ x for all t at once: Gx2[b,t,n,c] = sum_m adj[n,m] x[b,t,m,c]
// Tile: 64 bt x 64 n, both channels. grid (5, 24).
// ---------------------------------------------------------------------------
__global__ void __launch_bounds__(256) graph_x2_all(const float* __restrict__ adj,
                                                    const float* __restrict__ x) {
    int n0  = blockIdx.x * 64;
    int bt0 = blockIdx.y * 64;
    int tid = threadIdx.x;
    int tx  = tid & 15;    // bt group (4 each)
    int ty  = tid >> 4;    // n group  (4 each)

    __shared__ float adjs[32][65];     // [m][n]
    __shared__ float xs[64][65];       // [m*2+c][bt]

    float acc[4][4][2] = {};

    for (int m0 = 0; m0 < NN; m0 += 32) {
#pragma unroll
        for (int j = 0; j < 8; j++) {
            int lin = tid + j*256;
            int nl = lin >> 5, ml = lin & 31;
            int n = n0 + nl, m = m0 + ml;
            adjs[ml][nl] = (n < NN && m < NN) ? adj[(long)n*NN + m] : 0.0f;
        }
#pragma unroll
        for (int j = 0; j < 16; j++) {     // 64 bt x 64 (m,c) = 4096
            int lin = tid + j*256;
            int mc = lin & 63;             // m*2+c within tile
            int bt = lin >> 6;
            int m = m0 + (mc >> 1);
            xs[mc][bt] = (m < NN)
                ? x[((long)(bt0 + bt)*NN + m)*2 + (mc & 1)] : 0.0f;
        }
        __syncthreads();
#pragma unroll
        for (int ml = 0; ml < 32; ml++) {
            float a0 = adjs[ml][ty*4+0];
            float a1 = adjs[ml][ty*4+1];
            float a2 = adjs[ml][ty*4+2];
            float a3 = adjs[ml][ty*4+3];
#pragma unroll
            for (int jj = 0; jj < 4; jj++) {
                float x0 = xs[ml*2+0][tx*4+jj];
                float x1 = xs[ml*2+1][tx*4+jj];
                acc[0][jj][0] += a0*x0; acc[0][jj][1] += a0*x1;
                acc[1][jj][0] += a1*x0; acc[1][jj][1] += a1*x1;
                acc[2][jj][0] += a2*x0; acc[2][jj][1] += a2*x1;
                acc[3][jj][0] += a3*x0; acc[3][jj][1] += a3*x1;
            }
        }
        __syncthreads();
    }
#pragma unroll
    for (int i = 0; i < 4; i++) {
        int n = n0 + ty*4 + i;
        if (n >= NN) continue;
#pragma unroll
        for (int jj = 0; jj < 4; jj++) {
            int bt = bt0 + tx*4 + jj;
            *(float2*)&g_Gx2[((long)bt*NN + n)*2] =
                make_float2(acc[i][jj][0], acc[i][jj][1]);
        }
    }
}

// ---------------------------------------------------------------------------
// Graph propagation, 64 channels, 2 batches per block (adj tile reused).
// srcsel: 0=g_h, 1=g_zh, 2=g_seq0[t].  dstsel: 0=g_Gh, 1=g_Gzh, 2=g_Gxall[t]
// t < 0 -> t = blockIdx.z (batched over time). grid (5, 64[, T]).
// ---------------------------------------------------------------------------
__global__ void __launch_bounds__(256) graph64(const float* __restrict__ adj,
                                               int srcsel, int t, int dstsel) {
    if (t < 0) t = blockIdx.z;
    const float* src; long sstride; 
    if (srcsel == 0)      { src = g_h;  sstride = (long)NN*DOUT; }
    else if (srcsel == 1) { src = g_zh; sstride = (long)NN*DOUT; }
    else                  { src = g_seq0 + (long)t*NN*DOUT; sstride = (long)TT*NN*DOUT; }
    float* dst; long dstride;
    if (dstsel == 0)      { dst = g_Gh;  dstride = (long)NN*DOUT; }
    else if (dstsel == 1) { dst = g_Gzh; dstride = (long)NN*DOUT; }
    else                  { dst = g_Gxall + (long)t*NN*DOUT; dstride = (long)TT*NN*DOUT; }

    int b0 = blockIdx.y * 2;
    int n0 = blockIdx.x * 64;
    int tid = threadIdx.x;
    int tx = tid & 15;    // channel group (4 ch)
    int ty = tid >> 4;    // node group (4 nodes)

    __shared__ float adjs[32][65];
    __shared__ float srcs[2][32][64];

    unsigned long long acc2[2][4][2];
#pragma unroll
    for (int w = 0; w < 2; w++)
#pragma unroll
        for (int i = 0; i < 4; i++) { acc2[w][i][0] = 0ull; acc2[w][i][1] = 0ull; }

    const float* sb0 = src + (long)b0 * sstride;
    const float* sb1 = src + (long)(b0+1) * sstride;

    for (int m0 = 0; m0 < NN; m0 += 32) {
#pragma unroll
        for (int j = 0; j < 8; j++) {
            int lin = tid + j*256;
            int nl = lin >> 5, ml = lin & 31;
            int n = n0 + nl, m = m0 + ml;
            adjs[ml][nl] = (n < NN && m < NN) ? adj[(long)n*NN + m] : 0.0f;
        }
#pragma unroll
        for (int j = 0; j < 16; j++) {     // 2 x 32 x 64
            int lin = tid + j*256;
            int w  = lin >> 11;
            int ml = (lin >> 6) & 31;
            int c  = lin & 63;
            int m = m0 + ml;
            srcs[w][ml][c] = (m < NN)
                ? (w ? sb1 : sb0)[(long)m*DOUT + c] : 0.0f;
        }
        __syncthreads();
#pragma unroll
        for (int ml = 0; ml < 32; ml++) {
            unsigned long long s0x = *(const unsigned long long*)&srcs[0][ml][tx*4];
            unsigned long long s0y = *(const unsigned long long*)&srcs[0][ml][tx*4+2];
            unsigned long long s1x = *(const unsigned long long*)&srcs[1][ml][tx*4];
            unsigned long long s1y = *(const unsigned long long*)&srcs[1][ml][tx*4+2];
#pragma unroll
            for (int i = 0; i < 4; i++) {
                float a = adjs[ml][ty*4+i];
                unsigned long long ad = pk2(a, a);
                acc2[0][i][0] = ffma2(ad, s0x, acc2[0][i][0]);
                acc2[0][i][1] = ffma2(ad, s0y, acc2[0][i][1]);
                acc2[1][i][0] = ffma2(ad, s1x, acc2[1][i][0]);
                acc2[1][i][1] = ffma2(ad, s1y, acc2[1][i][1]);
            }
        }
        __syncthreads();
    }
#pragma unroll
    for (int i = 0; i < 4; i++) {
        int n = n0 + ty*4 + i;
        if (n >= NN) continue;
#pragma unroll
        for (int w = 0; w < 2; w++) {
            float4 v;
            unpk2(acc2[w][i][0], v.x, v.y);
            unpk2(acc2[w][i][1], v.z, v.w);
            *(float4*)&dst[(long)(b0+w)*dstride + (long)n*DOUT + tx*4] = v;
        }
    }
}

// ---------------------------------------------------------------------------
// A-row gather: A[b, kk] = [ x(CIN) | h_or_zh(64) | Gx(CIN) | Gh_or_Gzh(64) ]
// ---------------------------------------------------------------------------
template<int CIN, int MODE>
__device__ __forceinline__ float gatherA(int b, int n, int t, int kk) {
    constexpr int KD = 2*CIN + 2*DOUT;
    if (kk >= KD) return 0.0f;
    long xoff = ((long)b*TT + t)*NN*CIN + (long)n*CIN;
    long hoff = ((long)b*NN + n)*64;
    if (kk < CIN) {
        const float* xb = (CIN == 2) ? nullptr : g_seq0;  // resolved by caller for CIN==2
        return (CIN == 2) ? 0.0f : xb[xoff + kk];
    }
    if (kk < CIN + 64)
        return (MODE ? g_zh : g_h)[hoff + (kk - CIN)];
    if (kk < 2*CIN + 64)
        return ((CIN == 2) ? g_Gx2 : g_Gxall)[xoff + (kk - CIN - 64)];
    return (MODE ? g_Gzh : g_Gh)[hoff + (kk - 2*CIN - 64)];
}

// specialization wrapper handling the external x pointer for CIN==2
template<int CIN, int MODE>
__device__ __forceinline__ float gatherA2(const float* __restrict__ xext,
                                          int b, int n, int t, int kk) {
    if (CIN == 2 && kk < CIN) {
        long xoff = ((long)b*TT + t)*NN*CIN + (long)n*CIN;
        return xext[xoff + kk];
    }
    return gatherA<CIN, MODE>(b, n, t, kk);
}

// ---------------------------------------------------------------------------
// Gate GEMM (CO=128): one block per node, tile 128b x 128o, 8x8 per thread.
// Computes z (o<64) -> g_zh = z*h, and r (o>=64) -> g_r.
// ---------------------------------------------------------------------------
template<int CIN>
__global__ void __launch_bounds__(256) gate_k(const float* __restrict__ xext, int t) {
    constexpr int KD  = 2*CIN + 2*DOUT;         // 132 or 256
    constexpr int NKT = (KD + 31) / 32;
    const float* W    = (CIN == 2) ? g_Wg0 : g_Wg1;
    const float* bias = (CIN == 2) ? g_bg0 : g_bg1;

    int n  = blockIdx.x;
    int tid = threadIdx.x;
    int tx = tid & 15;   // o group
    int ty = tid >> 4;   // b group

    __shared__ float As[32][136];    // [kk][b] (pad: 4-way store conflict max)
    __shared__ float Ws[32][128];

    unsigned long long acc2[8][4];
#pragma unroll
    for (int i = 0; i < 8; i++)
#pragma unroll
        for (int j = 0; j < 4; j++) acc2[i][j] = 0ull;

    for (int kt = 0; kt < NKT; kt++) {
        int k0 = kt * 32;
#pragma unroll
        for (int j = 0; j < 16; j++) {          // A: 128b x 32kk
            int lin = tid + j*256;
            int kkl = lin & 31;
            int b   = lin >> 5;
            As[kkl][b] = gatherA2<CIN,0>(xext, b, n, t, k0 + kkl);
        }
#pragma unroll
        for (int j = 0; j < 16; j++) {          // W: 32kk x 128o
            int lin = tid + j*256;
            int col = lin & 127;
            int row = lin >> 7;
            int kk = k0 + row;
            Ws[row][col] = (kk < KD)
                ? W[(long)n*KD*128 + (long)kk*128 + col] : 0.0f;
        }
        __syncthreads();
#pragma unroll
        for (int k = 0; k < 32; k++) {
            ulonglong2 wlo = *(const ulonglong2*)&Ws[k][tx*4];
            ulonglong2 whi = *(const ulonglong2*)&Ws[k][64 + tx*4];
            float4 a_lo = *(const float4*)&As[k][ty*4];
            float4 a_hi = *(const float4*)&As[k][64 + ty*4];
            float av[8] = {a_lo.x, a_lo.y, a_lo.z, a_lo.w,
                           a_hi.x, a_hi.y, a_hi.z, a_hi.w};
#pragma unroll
            for (int i = 0; i < 8; i++) {
                unsigned long long ad = pk2(av[i], av[i]);
                acc2[i][0] = ffma2(ad, wlo.x, acc2[i][0]);
                acc2[i][1] = ffma2(ad, wlo.y, acc2[i][1]);
                acc2[i][2] = ffma2(ad, whi.x, acc2[i][2]);
                acc2[i][3] = ffma2(ad, whi.y, acc2[i][3]);
            }
        }
        __syncthreads();
    }

    float bl0 = bias[n*128 + tx*4 + 0], bl1 = bias[n*128 + tx*4 + 1];
    float bl2 = bias[n*128 + tx*4 + 2], bl3 = bias[n*128 + tx*4 + 3];
    float bh0 = bias[n*128 + 64 + tx*4 + 0], bh1 = bias[n*128 + 64 + tx*4 + 1];
    float bh2 = bias[n*128 + 64 + tx*4 + 2], bh3 = bias[n*128 + 64 + tx*4 + 3];

#pragma unroll
    for (int i = 0; i < 8; i++) {
        int b = (i < 4) ? (ty*4 + i) : (64 + ty*4 + (i - 4));
        long hb = ((long)b*NN + n)*64 + tx*4;
        float z0,z1,z2,z3, r0,r1,r2,r3;
        unpk2(acc2[i][0], z0, z1); unpk2(acc2[i][1], z2, z3);
        unpk2(acc2[i][2], r0, r1); unpk2(acc2[i][3], r2, r3);
        z0 = sigm(z0 + bl0); z1 = sigm(z1 + bl1);
        z2 = sigm(z2 + bl2); z3 = sigm(z3 + bl3);
        r0 = sigm(r0 + bh0); r1 = sigm(r1 + bh1);
        r2 = sigm(r2 + bh2); r3 = sigm(r3 + bh3);
        float4 hv = *(const float4*)&g_h[hb];
        *(float4*)&g_zh[hb] = make_float4(z0*hv.x, z1*hv.y, z2*hv.z, z3*hv.w);
        *(float4*)&g_r[hb]  = make_float4(r0, r1, r2, r3);
    }
}

// ---------------------------------------------------------------------------
// Candidate GEMM (CO=64) + GRU update epilogue. Tile 128b x 64o, 8x4/thread.
// ---------------------------------------------------------------------------
template<int CIN>
__global__ void __launch_bounds__(256) cand_k(const float* __restrict__ xext, int t,
                                              float* __restrict__ curOut,
                                              float* __restrict__ lastOut) {
    constexpr int KD  = 2*CIN + 2*DOUT;
    constexpr int NKT = (KD + 31) / 32;
    const float* W    = (CIN == 2) ? g_Wu0 : g_Wu1;
    const float* bias = (CIN == 2) ? g_bu0 : g_bu1;

    int n  = blockIdx.x;
    int tid = threadIdx.x;
    int tx = tid & 15;
    int ty = tid >> 4;

    __shared__ float As[32][136];
    __shared__ float Ws[32][64];

    unsigned long long acc2[8][2];
#pragma unroll
    for (int i = 0; i < 8; i++) { acc2[i][0] = 0ull; acc2[i][1] = 0ull; }

    for (int kt = 0; kt < NKT; kt++) {
        int k0 = kt * 32;
#pragma unroll
        for (int j = 0; j < 16; j++) {
            int lin = tid + j*256;
            int kkl = lin & 31;
            int b   = lin >> 5;
            As[kkl][b] = gatherA2<CIN,1>(xext, b, n, t, k0 + kkl);
        }
#pragma unroll
        for (int j = 0; j < 8; j++) {
            int lin = tid + j*256;
            int col = lin & 63;
            int row = lin >> 6;
            int kk = k0 + row;
            Ws[row][col] = (kk < KD)
                ? W[(long)n*KD*64 + (long)kk*64 + col] : 0.0f;
        }
        __syncthreads();
#pragma unroll
        for (int k = 0; k < 32; k++) {
            ulonglong2 w2 = *(const ulonglong2*)&Ws[k][tx*4];
            float4 a_lo = *(const float4*)&As[k][ty*4];
            float4 a_hi = *(const float4*)&As[k][64 + ty*4];
            float av[8] = {a_lo.x, a_lo.y, a_lo.z, a_lo.w,
                           a_hi.x, a_hi.y, a_hi.z, a_hi.w};
#pragma unroll
            for (int i = 0; i < 8; i++) {
                unsigned long long ad = pk2(av[i], av[i]);
                acc2[i][0] = ffma2(ad, w2.x, acc2[i][0]);
                acc2[i][1] = ffma2(ad, w2.y, acc2[i][1]);
            }
        }
        __syncthreads();
    }

    float b0 = bias[n*64 + tx*4 + 0], b1 = bias[n*64 + tx*4 + 1];
    float b2 = bias[n*64 + tx*4 + 2], b3 = bias[n*64 + tx*4 + 3];

#pragma unroll
    for (int i = 0; i < 8; i++) {
        int b = (i < 4) ? (ty*4 + i) : (64 + ty*4 + (i - 4));
        long hb = ((long)b*NN + n)*64 + tx*4;
        float c0,c1,c2,c3;
        unpk2(acc2[i][0], c0, c1); unpk2(acc2[i][1], c2, c3);
        c0 = tanhf(c0 + b0); c1 = tanhf(c1 + b1);
        c2 = tanhf(c2 + b2); c3 = tanhf(c3 + b3);
        float4 rv = *(const float4*)&g_r[hb];
        float4 hv = *(const float4*)&g_h[hb];
        float4 o;
        o.x = rv.x*hv.x + (1.0f - rv.x)*c0;
        o.y = rv.y*hv.y + (1.0f - rv.y)*c1;
        o.z = rv.z*hv.z + (1.0f - rv.z)*c2;
        o.w = rv.w*hv.w + (1.0f - rv.w)*c3;
        *(float4*)&g_h[hb] = o;
        float* seq = (CIN == 2) ? g_seq0 : curOut;
        *(float4*)&seq[((long)(b*TT + t))*NN*DOUT + (long)n*DOUT + tx*4] = o;
        if (lastOut) *(float4*)&lastOut[hb] = o;
    }
}

// ---------------------------------------------------------------------------
// Host driver
// ---------------------------------------------------------------------------
extern "C" void kernel_launch(void* const* d_in, const int* in_sizes, int n_in,
                              void* d_out, int out_size) {
    const float* x    = (const float*)d_in[0];
    const float* init = (const float*)d_in[1];
    const float* E    = (const float*)d_in[2];
    const float* adj  = (const float*)d_in[3];
    const float* wg0  = (const float*)d_in[4];
    const float* bg0  = (const float*)d_in[5];
    const float* wu0  = (const float*)d_in[6];
    const float* bu0  = (const float*)d_in[7];
    const float* wg1  = (const float*)d_in[8];
    const float* bg1  = (const float*)d_in[9];
    const float* wu1  = (const float*)d_in[10];
    const float* bu1  = (const float*)d_in[11];

    float* out      = (float*)d_out;
    float* lastBase = out + (long)CURSZ;

    // launch 0: precompute all per-node weights/biases
    prep_all<<<(unsigned)((C7 + 255) / 256), 256>>>(E, wg0, wu0, wg1, wu1,
                                                    bg0, bu0, bg1, bu1);
    // launch 1: h <- init[0]
    init_h<<<(BND + 255) / 256, 256>>>(init, 0);
    // launch 2: Gx2 for all timesteps
    graph_x2_all<<<dim3(5, BT/64), 256>>>(adj, x);

    dim3 gGrid(5, BB/2);

    // ---- layer 0 ---- (launch 3 = graph64, 4 = gate, 5 = graph64 <- ncu slot)
    for (int t = 0; t < TT; t++) {
        graph64<<<gGrid, 256>>>(adj, 0, t, 0);                       // Gh
        gate_k<2><<<NN, 256>>>(x, t);                                // z*h, r
        graph64<<<gGrid, 256>>>(adj, 1, t, 1);                       // Gzh
        cand_k<2><<<NN, 256>>>(x, t, nullptr,
                               (t == TT-1) ? lastBase : nullptr);    // h', seq0
    }
    // ---- layer 1 ----
    init_h<<<(BND + 255) / 256, 256>>>(init, 1);
    graph64<<<dim3(5, BB/2, TT), 256>>>(adj, 2, -1, 2);              // Gx all t
    for (int t = 0; t < TT; t++) {
        graph64<<<gGrid, 256>>>(adj, 0, t, 0);                       // Gh
        gate_k<64><<<NN, 256>>>(nullptr, t);
        graph64<<<gGrid, 256>>>(adj, 1, t, 1);                       // Gzh
        cand_k<64><<<NN, 256>>>(nullptr, t, out,
                                (t == TT-1) ? lastBase + BND : nullptr);
    }
}

// round 5
// speedup vs baseline: 1.1351x; 1.0772x over previous
#include <cuda_runtime.h>
#include <math.h>
#include <cstdint>

// Problem constants
#define NN   307
#define TT   12
#define BB   128
#define DIN  2
#define DOUT 64
#define DE   10

#define BND   (BB*NN*DOUT)        // 2,514,944
#define CURSZ (BB*TT*NN*DOUT)     // 30,179,328
#define BT    (BB*TT)             // 1536

// ---------------------------------------------------------------------------
// Device scratch
// ---------------------------------------------------------------------------
__device__ float g_Wg0[NN*132*128];
__device__ float g_Wu0[NN*132*64];
__device__ float g_Wg1[NN*256*128];
__device__ float g_Wu1[NN*256*64];
__device__ float g_bg0[NN*128];
__device__ float g_bu0[NN*64];
__device__ float g_bg1[NN*128];
__device__ float g_bu1[NN*64];

__device__ float g_h    [BND];        // hidden state [B,N,64]
__device__ float g_zh   [BND];        // z*h
__device__ float g_r    [BND];        // r gate
__device__ float g_Gx2  [BT*NN*DIN];  // adj @ x (layer0, all t)   [B,T,N,2]
__device__ float g_Gxall[CURSZ];      // adj @ seq0 (layer1 all t) [B,T,N,64]
__device__ float g_Gh   [BND];        // adj @ h
__device__ float g_Gzh  [BND];        // adj @ (z*h)
__device__ float g_seq0 [CURSZ];      // layer0 output sequence [B,T,N,64]

__device__ __forceinline__ float sigm(float v) { return 1.0f / (1.0f + expf(-v)); }

// packed fp32x2 helpers (bit-identical fp32 FMA at 2x pipe rate)
__device__ __forceinline__ unsigned long long pk2(float x, float y) {
    unsigned long long r;
    asm("mov.b64 %0, {%1, %2};" : "=l"(r) : "f"(x), "f"(y));
    return r;
}
__device__ __forceinline__ unsigned long long ffma2(unsigned long long a,
                                                    unsigned long long b,
                                                    unsigned long long c) {
    unsigned long long d;
    asm("fma.rn.f32x2 %0, %1, %2, %3;" : "=l"(d) : "l"(a), "l"(b), "l"(c));
    return d;
}
__device__ __forceinline__ void unpk2(unsigned long long v, float& lo, float& hi) {
    asm("mov.b64 {%0, %1}, %2;" : "=f"(lo), "=f"(hi) : "l"(v));
}

// ---------------------------------------------------------------------------
// Single-launch weight precompute (all 8 pools), plain [n][KD][NO] layout
// ---------------------------------------------------------------------------
#define S_WG0 (132*128)
#define S_WU0 (132*64)
#define S_WG1 (256*128)
#define S_WU1 (256*64)
#define C0 ((long)NN*S_WG0)
#define C1 (C0 + (long)NN*S_WU0)
#define C2 (C1 + (long)NN*S_WG1)
#define C3 (C2 + (long)NN*S_WU1)
#define C4 (C3 + (long)NN*128)
#define C5 (C4 + (long)NN*64)
#define C6 (C5 + (long)NN*128)
#define C7 (C6 + (long)NN*64)

__global__ void prep_all(const float* __restrict__ E,
                         const float* __restrict__ wg0, const float* __restrict__ wu0,
                         const float* __restrict__ wg1, const float* __restrict__ wu1,
                         const float* __restrict__ bg0, const float* __restrict__ bu0,
                         const float* __restrict__ bg1, const float* __restrict__ bu1) {
    long idx = (long)blockIdx.x * blockDim.x + threadIdx.x;
    if (idx >= C7) return;
    const float* pool; float* out; long loc; int S;
    if      (idx < C0) { pool = wg0; out = g_Wg0; loc = idx;      S = S_WG0; }
    else if (idx < C1) { pool = wu0; out = g_Wu0; loc = idx - C0; S = S_WU0; }
    else if (idx < C2) { pool = wg1; out = g_Wg1; loc = idx - C1; S = S_WG1; }
    else if (idx < C3) { pool = wu1; out = g_Wu1; loc = idx - C2; S = S_WU1; }
    else if (idx < C4) { pool = bg0; out = g_bg0; loc = idx - C3; S = 128;   }
    else if (idx < C5) { pool = bu0; out = g_bu0; loc = idx - C4; S = 64;    }
    else if (idx < C6) { pool = bg1; out = g_bg1; loc = idx - C5; S = 128;   }
    else               { pool = bu1; out = g_bu1; loc = idx - C6; S = 64;    }
    int n = (int)(loc / S);
    long j = loc - (long)n * S;
    float acc = 0.0f;
#pragma unroll
    for (int d = 0; d < DE; d++)
        acc += E[n*DE + d] * pool[(long)d*S + j];
    out[loc] = acc;
}

__global__ void init_h(const float* __restrict__ init, int l) {
    int i = blockIdx.x * blockDim.x + threadIdx.x;
    if (i < BND) g_h[i] = init[(long)l*BND + i];
}

// ---------------------------------------------------------------------------
// adj @ x for all timesteps (layer0, 2 channels): one launch
// ---------------------------------------------------------------------------
__global__ void __launch_bounds__(256) graph_x2_all(const float* __restrict__ adj,
                                                    const float* __restrict__ x) {
    int n0  = blockIdx.x * 64;
    int bt0 = blockIdx.y * 64;
    int tid = threadIdx.x;
    int tx  = tid & 15;
    int ty  = tid >> 4;

    __shared__ float adjs[32][65];
    __shared__ float xs[64][65];

    float acc[4][4][2] = {};

    for (int m0 = 0; m0 < NN; m0 += 32) {
#pragma unroll
        for (int j = 0; j < 8; j++) {
            int lin = tid + j*256;
            int nl = lin >> 5, ml = lin & 31;
            int n = n0 + nl, m = m0 + ml;
            adjs[ml][nl] = (n < NN && m < NN) ? adj[(long)n*NN + m] : 0.0f;
        }
#pragma unroll
        for (int j = 0; j < 16; j++) {
            int lin = tid + j*256;
            int mc = lin & 63;
            int bt = lin >> 6;
            int m = m0 + (mc >> 1);
            xs[mc][bt] = (m < NN) ? x[((long)(bt0 + bt)*NN + m)*2 + (mc & 1)] : 0.0f;
        }
        __syncthreads();
#pragma unroll
        for (int ml = 0; ml < 32; ml++) {
            float a0 = adjs[ml][ty*4+0];
            float a1 = adjs[ml][ty*4+1];
            float a2 = adjs[ml][ty*4+2];
            float a3 = adjs[ml][ty*4+3];
#pragma unroll
            for (int jj = 0; jj < 4; jj++) {
                float x0 = xs[ml*2+0][tx*4+jj];
                float x1 = xs[ml*2+1][tx*4+jj];
                acc[0][jj][0] += a0*x0; acc[0][jj][1] += a0*x1;
                acc[1][jj][0] += a1*x0; acc[1][jj][1] += a1*x1;
                acc[2][jj][0] += a2*x0; acc[2][jj][1] += a2*x1;
                acc[3][jj][0] += a3*x0; acc[3][jj][1] += a3*x1;
            }
        }
        __syncthreads();
    }
#pragma unroll
    for (int i = 0; i < 4; i++) {
        int n = n0 + ty*4 + i;
        if (n >= NN) continue;
#pragma unroll
        for (int jj = 0; jj < 4; jj++) {
            int bt = bt0 + tx*4 + jj;
            *(float2*)&g_Gx2[((long)bt*NN + n)*2] =
                make_float2(acc[i][jj][0], acc[i][jj][1]);
        }
    }
}

// ---------------------------------------------------------------------------
// Graph propagation, 64 channels. 128-thread blocks, tile 32n x 64c x 2b.
// grid (10, 64 [, T]).  srcsel: 0=g_h, 1=g_zh, 2=g_seq0[t]
// dstsel: 0=g_Gh, 1=g_Gzh, 2=g_Gxall[t].  t<0 -> t=blockIdx.z
// ---------------------------------------------------------------------------
__global__ void __launch_bounds__(128) graph64(const float* __restrict__ adj,
                                               int srcsel, int t, int dstsel) {
    if (t < 0) t = blockIdx.z;
    const float* src; long sstride;
    if (srcsel == 0)      { src = g_h;  sstride = (long)NN*DOUT; }
    else if (srcsel == 1) { src = g_zh; sstride = (long)NN*DOUT; }
    else                  { src = g_seq0 + (long)t*NN*DOUT; sstride = (long)TT*NN*DOUT; }
    float* dst; long dstride;
    if (dstsel == 0)      { dst = g_Gh;  dstride = (long)NN*DOUT; }
    else if (dstsel == 1) { dst = g_Gzh; dstride = (long)NN*DOUT; }
    else                  { dst = g_Gxall + (long)t*NN*DOUT; dstride = (long)TT*NN*DOUT; }

    int n0 = blockIdx.x * 32;
    int b0 = blockIdx.y * 2;
    int tid = threadIdx.x;
    int tx = tid & 15;          // channel group (4 ch)
    int ty = tid >> 4;          // node group (4 nodes), 0..7 -> 32 n

    __shared__ float adjs[32][33];     // [m][n], pad 33: conflict-free col stores
    __shared__ float srcs[2][32][64];  // [b][m][c]

    unsigned long long acc2[4][2][2];  // [n_i][b_w][c_half]
#pragma unroll
    for (int i = 0; i < 4; i++)
#pragma unroll
        for (int w = 0; w < 2; w++) { acc2[i][w][0] = 0ull; acc2[i][w][1] = 0ull; }

    const float* sb0 = src + (long)b0 * sstride;
    const float* sb1 = src + (long)(b0+1) * sstride;

    for (int m0 = 0; m0 < NN; m0 += 32) {
        // adj tile 32n x 32m  (1024 scalars / 128 thr = 8)
#pragma unroll
        for (int j = 0; j < 8; j++) {
            int lin = tid + j*128;
            int ml = lin & 31, nl = lin >> 5;
            int n = n0 + nl, m = m0 + ml;
            adjs[ml][nl] = (n < NN && m < NN) ? adj[(long)n*NN + m] : 0.0f;
        }
        // src tiles: 2 x 32m x 64c = 1024 float4 / 128 thr = 8
#pragma unroll
        for (int j = 0; j < 8; j++) {
            int lin = tid + j*128;
            int c4 = lin & 15;
            int ml = (lin >> 4) & 31;
            int w  = lin >> 9;
            int m = m0 + ml;
            float4 v = make_float4(0.f, 0.f, 0.f, 0.f);
            if (m < NN)
                v = *(const float4*)&(w ? sb1 : sb0)[(long)m*DOUT + c4*4];
            *(float4*)&srcs[w][ml][c4*4] = v;
        }
        __syncthreads();
#pragma unroll
        for (int ml = 0; ml < 32; ml++) {
            ulonglong2 s0 = *(const ulonglong2*)&srcs[0][ml][tx*4];
            ulonglong2 s1 = *(const ulonglong2*)&srcs[1][ml][tx*4];
#pragma unroll
            for (int i = 0; i < 4; i++) {
                float a = adjs[ml][ty*4+i];
                unsigned long long ad = pk2(a, a);
                acc2[i][0][0] = ffma2(ad, s0.x, acc2[i][0][0]);
                acc2[i][0][1] = ffma2(ad, s0.y, acc2[i][0][1]);
                acc2[i][1][0] = ffma2(ad, s1.x, acc2[i][1][0]);
                acc2[i][1][1] = ffma2(ad, s1.y, acc2[i][1][1]);
            }
        }
        __syncthreads();
    }
#pragma unroll
    for (int i = 0; i < 4; i++) {
        int n = n0 + ty*4 + i;
        if (n >= NN) continue;
#pragma unroll
        for (int w = 0; w < 2; w++) {
            float4 v;
            unpk2(acc2[i][w][0], v.x, v.y);
            unpk2(acc2[i][w][1], v.z, v.w);
            *(float4*)&dst[(long)(b0+w)*dstride + (long)n*DOUT + tx*4] = v;
        }
    }
}

// ---------------------------------------------------------------------------
// A-row gather: A[b, kk] = [ x(CIN) | h_or_zh(64) | Gx(CIN) | Gh_or_Gzh(64) ]
// ---------------------------------------------------------------------------
template<int CIN, int MODE>
__device__ __forceinline__ float gatherA(const float* __restrict__ xext,
                                         int b, int n, int t, int kk) {
    constexpr int KD = 2*CIN + 2*DOUT;
    if (kk >= KD) return 0.0f;
    long xoff = ((long)b*TT + t)*NN*CIN + (long)n*CIN;
    long hoff = ((long)b*NN + n)*64;
    if (kk < CIN)
        return (CIN == 2) ? xext[xoff + kk] : g_seq0[xoff + kk];
    if (kk < CIN + 64)
        return (MODE ? g_zh : g_h)[hoff + (kk - CIN)];
    if (kk < 2*CIN + 64)
        return ((CIN == 2) ? g_Gx2 : g_Gxall)[xoff + (kk - CIN - 64)];
    return (MODE ? g_Gzh : g_Gh)[hoff + (kk - 2*CIN - 64)];
}

// ---------------------------------------------------------------------------
// Gate GEMM: tile 64b x 64o, 128 threads, thread tile 8b x 4o.
// grid (NN, 2 bhalf, 2 ohalf).  oh=0: z -> g_zh = z*h.  oh=1: r -> g_r.
// ---------------------------------------------------------------------------
template<int CIN>
__global__ void __launch_bounds__(128) gate_k(const float* __restrict__ xext, int t) {
    constexpr int KD  = 2*CIN + 2*DOUT;         // 132 or 256
    constexpr int NKT = (KD + 31) / 32;         // 5 or 8
    const float* W    = (CIN == 2) ? g_Wg0 : g_Wg1;
    const float* bias = (CIN == 2) ? g_bg0 : g_bg1;

    int n  = blockIdx.x;
    int bh = blockIdx.y;        // batch half
    int oh = blockIdx.z;        // output half: 0=z, 1=r
    int tid = threadIdx.x;
    int tx = tid & 15;          // o group (4 cols)
    int ty = tid >> 4;          // b group (8 rows)

    __shared__ float As[64][33];   // [b][kk], pad 33
    __shared__ float Ws[32][64];   // [kk][o]

    unsigned long long acc2[8][2];
#pragma unroll
    for (int i = 0; i < 8; i++) { acc2[i][0] = 0ull; acc2[i][1] = 0ull; }

    for (int kt = 0; kt < NKT; kt++) {
        int k0 = kt * 32;
        // A: 64b x 32kk gathered (2048 / 128 = 16)
#pragma unroll
        for (int j = 0; j < 16; j++) {
            int lin = tid + j*128;
            int kl = lin & 31;
            int b  = lin >> 5;
            As[b][kl] = gatherA<CIN,0>(xext, bh*64 + b, n, t, k0 + kl);
        }
        // W: 32kk x 64o vectorized (512 float4 / 128 = 4)
#pragma unroll
        for (int j = 0; j < 4; j++) {
            int lin = tid + j*128;
            int c4  = lin & 15;
            int row = lin >> 4;
            int kk = k0 + row;
            float4 v = make_float4(0.f, 0.f, 0.f, 0.f);
            if (kk < KD)
                v = *(const float4*)&W[((long)n*KD + kk)*128 + oh*64 + c4*4];
            *(float4*)&Ws[row][c4*4] = v;
        }
        __syncthreads();
#pragma unroll
        for (int k = 0; k < 32; k++) {
            ulonglong2 w2 = *(const ulonglong2*)&Ws[k][tx*4];
#pragma unroll
            for (int i = 0; i < 8; i++) {
                float a = As[ty*8 + i][k];
                unsigned long long ad = pk2(a, a);
                acc2[i][0] = ffma2(ad, w2.x, acc2[i][0]);
                acc2[i][1] = ffma2(ad, w2.y, acc2[i][1]);
            }
        }
        __syncthreads();
    }

    float4 bv = *(const float4*)&bias[n*128 + oh*64 + tx*4];
#pragma unroll
    for (int i = 0; i < 8; i++) {
        int b = bh*64 + ty*8 + i;
        long hb = ((long)b*NN + n)*64 + tx*4;
        float v0, v1, v2, v3;
        unpk2(acc2[i][0], v0, v1);
        unpk2(acc2[i][1], v2, v3);
        v0 = sigm(v0 + bv.x); v1 = sigm(v1 + bv.y);
        v2 = sigm(v2 + bv.z); v3 = sigm(v3 + bv.w);
        if (oh == 0) {
            float4 hv = *(const float4*)&g_h[hb];
            *(float4*)&g_zh[hb] = make_float4(v0*hv.x, v1*hv.y, v2*hv.z, v3*hv.w);
        } else {
            *(float4*)&g_r[hb] = make_float4(v0, v1, v2, v3);
        }
    }
}

// ---------------------------------------------------------------------------
// Candidate GEMM (NO=64) + GRU update. tile 64b x 64o, grid (NN, 2).
// ---------------------------------------------------------------------------
template<int CIN>
__global__ void __launch_bounds__(128) cand_k(const float* __restrict__ xext, int t,
                                              float* __restrict__ curOut,
                                              float* __restrict__ lastOut) {
    constexpr int KD  = 2*CIN + 2*DOUT;
    constexpr int NKT = (KD + 31) / 32;
    const float* W    = (CIN == 2) ? g_Wu0 : g_Wu1;
    const float* bias = (CIN == 2) ? g_bu0 : g_bu1;

    int n  = blockIdx.x;
    int bh = blockIdx.y;
    int tid = threadIdx.x;
    int tx = tid & 15;
    int ty = tid >> 4;

    __shared__ float As[64][33];
    __shared__ float Ws[32][64];

    unsigned long long acc2[8][2];
#pragma unroll
    for (int i = 0; i < 8; i++) { acc2[i][0] = 0ull; acc2[i][1] = 0ull; }

    for (int kt = 0; kt < NKT; kt++) {
        int k0 = kt * 32;
#pragma unroll
        for (int j = 0; j < 16; j++) {
            int lin = tid + j*128;
            int kl = lin & 31;
            int b  = lin >> 5;
            As[b][kl] = gatherA<CIN,1>(xext, bh*64 + b, n, t, k0 + kl);
        }
#pragma unroll
        for (int j = 0; j < 4; j++) {
            int lin = tid + j*128;
            int c4  = lin & 15;
            int row = lin >> 4;
            int kk = k0 + row;
            float4 v = make_float4(0.f, 0.f, 0.f, 0.f);
            if (kk < KD)
                v = *(const float4*)&W[((long)n*KD + kk)*64 + c4*4];
            *(float4*)&Ws[row][c4*4] = v;
        }
        __syncthreads();
#pragma unroll
        for (int k = 0; k < 32; k++) {
            ulonglong2 w2 = *(const ulonglong2*)&Ws[k][tx*4];
#pragma unroll
            for (int i = 0; i < 8; i++) {
                float a = As[ty*8 + i][k];
                unsigned long long ad = pk2(a, a);
                acc2[i][0] = ffma2(ad, w2.x, acc2[i][0]);
                acc2[i][1] = ffma2(ad, w2.y, acc2[i][1]);
            }
        }
        __syncthreads();
    }

    float4 bv = *(const float4*)&bias[n*64 + tx*4];
#pragma unroll
    for (int i = 0; i < 8; i++) {
        int b = bh*64 + ty*8 + i;
        long hb = ((long)b*NN + n)*64 + tx*4;
        float c0, c1, c2, c3;
        unpk2(acc2[i][0], c0, c1);
        unpk2(acc2[i][1], c2, c3);
        c0 = tanhf(c0 + bv.x); c1 = tanhf(c1 + bv.y);
        c2 = tanhf(c2 + bv.z); c3 = tanhf(c3 + bv.w);
        float4 rv = *(const float4*)&g_r[hb];
        float4 hv = *(const float4*)&g_h[hb];
        float4 o;
        o.x = rv.x*hv.x + (1.0f - rv.x)*c0;
        o.y = rv.y*hv.y + (1.0f - rv.y)*c1;
        o.z = rv.z*hv.z + (1.0f - rv.z)*c2;
        o.w = rv.w*hv.w + (1.0f - rv.w)*c3;
        *(float4*)&g_h[hb] = o;
        float* seq = (CIN == 2) ? g_seq0 : curOut;
        *(float4*)&seq[((long)(b*TT + t))*NN*DOUT + (long)n*DOUT + tx*4] = o;
        if (lastOut) *(float4*)&lastOut[hb] = o;
    }
}

// ---------------------------------------------------------------------------
// Host driver — graph-capturable (kernel launches only, default stream)
// ---------------------------------------------------------------------------
extern "C" void kernel_launch(void* const* d_in, const int* in_sizes, int n_in,
                              void* d_out, int out_size) {
    const float* x    = (const float*)d_in[0];
    const float* init = (const float*)d_in[1];
    const float* E    = (const float*)d_in[2];
    const float* adj  = (const float*)d_in[3];
    const float* wg0  = (const float*)d_in[4];
    const float* bg0  = (const float*)d_in[5];
    const float* wu0  = (const float*)d_in[6];
    const float* bu0  = (const float*)d_in[7];
    const float* wg1  = (const float*)d_in[8];
    const float* bg1  = (const float*)d_in[9];
    const float* wu1  = (const float*)d_in[10];
    const float* bu1  = (const float*)d_in[11];

    float* out      = (float*)d_out;
    float* lastBase = out + (long)CURSZ;

    prep_all<<<(unsigned)((C7 + 255) / 256), 256>>>(E, wg0, wu0, wg1, wu1,
                                                    bg0, bu0, bg1, bu1);
    init_h<<<(BND + 255) / 256, 256>>>(init, 0);
    graph_x2_all<<<dim3(5, BT/64), 256>>>(adj, x);

    dim3 gGrid(10, BB/2);            // graph64: 640 blocks x 128 thr

    // ---- layer 0 ----
    for (int t = 0; t < TT; t++) {
        graph64<<<gGrid, 128>>>(adj, 0, t, 0);                        // Gh
        gate_k<2><<<dim3(NN,2,2), 128>>>(x, t);                       // z*h, r
        graph64<<<gGrid, 128>>>(adj, 1, t, 1);                        // Gzh
        cand_k<2><<<dim3(NN,2), 128>>>(x, t, nullptr,
                        (t == TT-1) ? lastBase : nullptr);            // h', seq0
    }
    // ---- layer 1 ----
    init_h<<<(BND + 255) / 256, 256>>>(init, 1);
    graph64<<<dim3(10, BB/2, TT), 128>>>(adj, 2, -1, 2);              // Gx all t
    for (int t = 0; t < TT; t++) {
        graph64<<<gGrid, 128>>>(adj, 0, t, 0);                        // Gh
        gate_k<64><<<dim3(NN,2,2), 128>>>(nullptr, t);
        graph64<<<gGrid, 128>>>(adj, 1, t, 1);                        // Gzh
        cand_k<64><<<dim3(NN,2), 128>>>(nullptr, t, out,
                        (t == TT-1) ? lastBase + BND : nullptr);
    }
}

// round 6
// speedup vs baseline: 1.3317x; 1.1732x over previous
#include <cuda_runtime.h>
#include <math.h>
#include <cstdint>

// Problem constants
#define NN   307
#define TT   12
#define BB   128
#define DIN  2
#define DOUT 64
#define DE   10

#define BND   (BB*NN*DOUT)        // 2,514,944
#define CURSZ (BB*TT*NN*DOUT)     // 30,179,328
#define BT    (BB*TT)             // 1536

// ---------------------------------------------------------------------------
// Device scratch
// ---------------------------------------------------------------------------
__device__ float g_Wg0[NN*132*128];
__device__ float g_Wu0[NN*132*64];
__device__ float g_Wg1[NN*256*128];
__device__ float g_Wu1[NN*256*64];
__device__ float g_bg0[NN*128];
__device__ float g_bu0[NN*64];
__device__ float g_bg1[NN*128];
__device__ float g_bu1[NN*64];

__device__ float g_h    [BND];        // hidden state [B,N,64]
__device__ float g_zh   [BND];        // z*h
__device__ float g_r    [BND];        // r gate
__device__ float g_Gx2  [BT*NN*DIN];  // adj @ x (layer0, all t)   [B,T,N,2]
__device__ float g_Gxall[CURSZ];      // adj @ seq0 (layer1 all t) [B,T,N,64]
__device__ float g_Gh   [BND];        // adj @ h
__device__ float g_Gzh  [BND];        // adj @ (z*h)
__device__ float g_seq0 [CURSZ];      // layer0 output sequence [B,T,N,64]

__device__ __forceinline__ float sigm(float v) { return 1.0f / (1.0f + expf(-v)); }

// packed fp32x2 helpers (bit-identical fp32 FMA at 2x pipe rate)
__device__ __forceinline__ unsigned long long pk2(float x, float y) {
    unsigned long long r;
    asm("mov.b64 %0, {%1, %2};" : "=l"(r) : "f"(x), "f"(y));
    return r;
}
__device__ __forceinline__ unsigned long long ffma2(unsigned long long a,
                                                    unsigned long long b,
                                                    unsigned long long c) {
    unsigned long long d;
    asm("fma.rn.f32x2 %0, %1, %2, %3;" : "=l"(d) : "l"(a), "l"(b), "l"(c));
    return d;
}
__device__ __forceinline__ void unpk2(unsigned long long v, float& lo, float& hi) {
    asm("mov.b64 {%0, %1}, %2;" : "=f"(lo), "=f"(hi) : "l"(v));
}

// ---------------------------------------------------------------------------
// Single-launch weight precompute (all 8 pools), plain [n][KD][NO] layout
// ---------------------------------------------------------------------------
#define S_WG0 (132*128)
#define S_WU0 (132*64)
#define S_WG1 (256*128)
#define S_WU1 (256*64)
#define C0 ((long)NN*S_WG0)
#define C1 (C0 + (long)NN*S_WU0)
#define C2 (C1 + (long)NN*S_WG1)
#define C3 (C2 + (long)NN*S_WU1)
#define C4 (C3 + (long)NN*128)
#define C5 (C4 + (long)NN*64)
#define C6 (C5 + (long)NN*128)
#define C7 (C6 + (long)NN*64)

__global__ void prep_all(const float* __restrict__ E,
                         const float* __restrict__ wg0, const float* __restrict__ wu0,
                         const float* __restrict__ wg1, const float* __restrict__ wu1,
                         const float* __restrict__ bg0, const float* __restrict__ bu0,
                         const float* __restrict__ bg1, const float* __restrict__ bu1) {
    long idx = (long)blockIdx.x * blockDim.x + threadIdx.x;
    if (idx >= C7) return;
    const float* pool; float* out; long loc; int S;
    if      (idx < C0) { pool = wg0; out = g_Wg0; loc = idx;      S = S_WG0; }
    else if (idx < C1) { pool = wu0; out = g_Wu0; loc = idx - C0; S = S_WU0; }
    else if (idx < C2) { pool = wg1; out = g_Wg1; loc = idx - C1; S = S_WG1; }
    else if (idx < C3) { pool = wu1; out = g_Wu1; loc = idx - C2; S = S_WU1; }
    else if (idx < C4) { pool = bg0; out = g_bg0; loc = idx - C3; S = 128;   }
    else if (idx < C5) { pool = bu0; out = g_bu0; loc = idx - C4; S = 64;    }
    else if (idx < C6) { pool = bg1; out = g_bg1; loc = idx - C5; S = 128;   }
    else               { pool = bu1; out = g_bu1; loc = idx - C6; S = 64;    }
    int n = (int)(loc / S);
    long j = loc - (long)n * S;
    float acc = 0.0f;
#pragma unroll
    for (int d = 0; d < DE; d++)
        acc += E[n*DE + d] * pool[(long)d*S + j];
    out[loc] = acc;
}

__global__ void init_h(const float* __restrict__ init, int l) {
    int i = blockIdx.x * blockDim.x + threadIdx.x;
    if (i < BND) g_h[i] = init[(long)l*BND + i];
}

// ---------------------------------------------------------------------------
// adj @ x for all timesteps (layer0, 2 channels): one launch
// ---------------------------------------------------------------------------
__global__ void __launch_bounds__(256) graph_x2_all(const float* __restrict__ adj,
                                                    const float* __restrict__ x) {
    int n0  = blockIdx.x * 64;
    int bt0 = blockIdx.y * 64;
    int tid = threadIdx.x;
    int tx  = tid & 15;
    int ty  = tid >> 4;

    __shared__ float adjs[32][65];
    __shared__ float xs[64][65];

    float acc[4][4][2] = {};

    for (int m0 = 0; m0 < NN; m0 += 32) {
#pragma unroll
        for (int j = 0; j < 8; j++) {
            int lin = tid + j*256;
            int nl = lin >> 5, ml = lin & 31;
            int n = n0 + nl, m = m0 + ml;
            adjs[ml][nl] = (n < NN && m < NN) ? adj[(long)n*NN + m] : 0.0f;
        }
#pragma unroll
        for (int j = 0; j < 16; j++) {
            int lin = tid + j*256;
            int mc = lin & 63;
            int bt = lin >> 6;
            int m = m0 + (mc >> 1);
            xs[mc][bt] = (m < NN) ? x[((long)(bt0 + bt)*NN + m)*2 + (mc & 1)] : 0.0f;
        }
        __syncthreads();
#pragma unroll
        for (int ml = 0; ml < 32; ml++) {
            float a0 = adjs[ml][ty*4+0];
            float a1 = adjs[ml][ty*4+1];
            float a2 = adjs[ml][ty*4+2];
            float a3 = adjs[ml][ty*4+3];
#pragma unroll
            for (int jj = 0; jj < 4; jj++) {
                float x0 = xs[ml*2+0][tx*4+jj];
                float x1 = xs[ml*2+1][tx*4+jj];
                acc[0][jj][0] += a0*x0; acc[0][jj][1] += a0*x1;
                acc[1][jj][0] += a1*x0; acc[1][jj][1] += a1*x1;
                acc[2][jj][0] += a2*x0; acc[2][jj][1] += a2*x1;
                acc[3][jj][0] += a3*x0; acc[3][jj][1] += a3*x1;
            }
        }
        __syncthreads();
    }
#pragma unroll
    for (int i = 0; i < 4; i++) {
        int n = n0 + ty*4 + i;
        if (n >= NN) continue;
#pragma unroll
        for (int jj = 0; jj < 4; jj++) {
            int bt = bt0 + tx*4 + jj;
            *(float2*)&g_Gx2[((long)bt*NN + n)*2] =
                make_float2(acc[i][jj][0], acc[i][jj][1]);
        }
    }
}

// ---------------------------------------------------------------------------
// Graph propagation, 64 channels. 128-thread blocks, tile 32n x 64c x 2b.
// launch_bounds(128,6) to cap regs (~80) and lift occupancy (was 96 regs,
// 25.5% occ, issue 40.7%).
// ---------------------------------------------------------------------------
__global__ void __launch_bounds__(128, 6) graph64(const float* __restrict__ adj,
                                                  int srcsel, int t, int dstsel) {
    if (t < 0) t = blockIdx.z;
    const float* src; long sstride;
    if (srcsel == 0)      { src = g_h;  sstride = (long)NN*DOUT; }
    else if (srcsel == 1) { src = g_zh; sstride = (long)NN*DOUT; }
    else                  { src = g_seq0 + (long)t*NN*DOUT; sstride = (long)TT*NN*DOUT; }
    float* dst; long dstride;
    if (dstsel == 0)      { dst = g_Gh;  dstride = (long)NN*DOUT; }
    else if (dstsel == 1) { dst = g_Gzh; dstride = (long)NN*DOUT; }
    else                  { dst = g_Gxall + (long)t*NN*DOUT; dstride = (long)TT*NN*DOUT; }

    int n0 = blockIdx.x * 32;
    int b0 = blockIdx.y * 2;
    int tid = threadIdx.x;
    int tx = tid & 15;          // channel group (4 ch)
    int ty = tid >> 4;          // node group (4 nodes)

    __shared__ float adjs[32][33];     // [m][n]
    __shared__ float srcs[2][32][64];  // [b][m][c]

    unsigned long long acc2[4][2][2];
#pragma unroll
    for (int i = 0; i < 4; i++)
#pragma unroll
        for (int w = 0; w < 2; w++) { acc2[i][w][0] = 0ull; acc2[i][w][1] = 0ull; }

    const float* sb0 = src + (long)b0 * sstride;
    const float* sb1 = src + (long)(b0+1) * sstride;

    for (int m0 = 0; m0 < NN; m0 += 32) {
#pragma unroll
        for (int j = 0; j < 8; j++) {
            int lin = tid + j*128;
            int ml = lin & 31, nl = lin >> 5;
            int n = n0 + nl, m = m0 + ml;
            adjs[ml][nl] = (n < NN && m < NN) ? adj[(long)n*NN + m] : 0.0f;
        }
#pragma unroll
        for (int j = 0; j < 8; j++) {
            int lin = tid + j*128;
            int c4 = lin & 15;
            int ml = (lin >> 4) & 31;
            int w  = lin >> 9;
            int m = m0 + ml;
            float4 v = make_float4(0.f, 0.f, 0.f, 0.f);
            if (m < NN)
                v = *(const float4*)&(w ? sb1 : sb0)[(long)m*DOUT + c4*4];
            *(float4*)&srcs[w][ml][c4*4] = v;
        }
        __syncthreads();
#pragma unroll
        for (int ml = 0; ml < 32; ml++) {
            ulonglong2 s0 = *(const ulonglong2*)&srcs[0][ml][tx*4];
            ulonglong2 s1 = *(const ulonglong2*)&srcs[1][ml][tx*4];
#pragma unroll
            for (int i = 0; i < 4; i++) {
                float a = adjs[ml][ty*4+i];
                unsigned long long ad = pk2(a, a);
                acc2[i][0][0] = ffma2(ad, s0.x, acc2[i][0][0]);
                acc2[i][0][1] = ffma2(ad, s0.y, acc2[i][0][1]);
                acc2[i][1][0] = ffma2(ad, s1.x, acc2[i][1][0]);
                acc2[i][1][1] = ffma2(ad, s1.y, acc2[i][1][1]);
            }
        }
        __syncthreads();
    }
#pragma unroll
    for (int i = 0; i < 4; i++) {
        int n = n0 + ty*4 + i;
        if (n >= NN) continue;
#pragma unroll
        for (int w = 0; w < 2; w++) {
            float4 v;
            unpk2(acc2[i][w][0], v.x, v.y);
            unpk2(acc2[i][w][1], v.z, v.w);
            *(float4*)&dst[(long)(b0+w)*dstride + (long)n*DOUT + tx*4] = v;
        }
    }
}

// ---------------------------------------------------------------------------
// A-row gather: A[b, kk] = [ x(CIN) | h_or_zh(64) | Gx(CIN) | Gh_or_Gzh(64) ]
// ---------------------------------------------------------------------------
template<int CIN, int MODE>
__device__ __forceinline__ float gatherA(const float* __restrict__ xext,
                                         int b, int n, int t, int kk) {
    constexpr int KD = 2*CIN + 2*DOUT;
    if (kk >= KD) return 0.0f;
    long xoff = ((long)b*TT + t)*NN*CIN + (long)n*CIN;
    long hoff = ((long)b*NN + n)*64;
    if (kk < CIN)
        return (CIN == 2) ? xext[xoff + kk] : g_seq0[xoff + kk];
    if (kk < CIN + 64)
        return (MODE ? g_zh : g_h)[hoff + (kk - CIN)];
    if (kk < 2*CIN + 64)
        return ((CIN == 2) ? g_Gx2 : g_Gxall)[xoff + (kk - CIN - 64)];
    return (MODE ? g_Gzh : g_Gh)[hoff + (kk - 2*CIN - 64)];
}

// ---------------------------------------------------------------------------
// Gate GEMM: tile 64b x 64o, 128 threads, thread tile 8b x 4o.
// A in smem as [kk][b] (pad 68): compute loads are broadcast LDS.128.
// grid (NN, 2 bhalf, 2 ohalf).  oh=0: z -> g_zh = z*h.  oh=1: r -> g_r.
// ---------------------------------------------------------------------------
template<int CIN>
__global__ void __launch_bounds__(128, 8) gate_k(const float* __restrict__ xext, int t) {
    constexpr int KD  = 2*CIN + 2*DOUT;         // 132 or 256
    constexpr int NKT = (KD + 31) / 32;         // 5 or 8
    const float* W    = (CIN == 2) ? g_Wg0 : g_Wg1;
    const float* bias = (CIN == 2) ? g_bg0 : g_bg1;

    int n  = blockIdx.x;
    int bh = blockIdx.y;        // batch half
    int oh = blockIdx.z;        // output half: 0=z, 1=r
    int tid = threadIdx.x;
    int tx = tid & 15;          // o group (4 cols)
    int ty = tid >> 4;          // b group (8 rows)

    __shared__ float As[32][68];   // [kk][b], pad 68 (16B-aligned rows)
    __shared__ float Ws[32][68];   // [kk][o]

    unsigned long long acc2[8][2];
#pragma unroll
    for (int i = 0; i < 8; i++) { acc2[i][0] = 0ull; acc2[i][1] = 0ull; }

    for (int kt = 0; kt < NKT; kt++) {
        int k0 = kt * 32;
        // A: 64b x 32kk gathered, stored transposed [kk][b]
#pragma unroll
        for (int j = 0; j < 16; j++) {
            int lin = tid + j*128;
            int kl = lin & 31;
            int b  = lin >> 5;
            As[kl][b] = gatherA<CIN,0>(xext, bh*64 + b, n, t, k0 + kl);
        }
        // W: 32kk x 64o vectorized
#pragma unroll
        for (int j = 0; j < 4; j++) {
            int lin = tid + j*128;
            int c4  = lin & 15;
            int row = lin >> 4;
            int kk = k0 + row;
            float4 v = make_float4(0.f, 0.f, 0.f, 0.f);
            if (kk < KD)
                v = *(const float4*)&W[((long)n*KD + kk)*128 + oh*64 + c4*4];
            *(float4*)&Ws[row][c4*4] = v;
        }
        __syncthreads();
#pragma unroll
        for (int k = 0; k < 32; k++) {
            float4 aLo = *(const float4*)&As[k][ty*8];
            float4 aHi = *(const float4*)&As[k][ty*8 + 4];
            ulonglong2 w2 = *(const ulonglong2*)&Ws[k][tx*4];
            float av[8] = {aLo.x, aLo.y, aLo.z, aLo.w,
                           aHi.x, aHi.y, aHi.z, aHi.w};
#pragma unroll
            for (int i = 0; i < 8; i++) {
                unsigned long long ad = pk2(av[i], av[i]);
                acc2[i][0] = ffma2(ad, w2.x, acc2[i][0]);
                acc2[i][1] = ffma2(ad, w2.y, acc2[i][1]);
            }
        }
        __syncthreads();
    }

    float4 bv = *(const float4*)&bias[n*128 + oh*64 + tx*4];
#pragma unroll
    for (int i = 0; i < 8; i++) {
        int b = bh*64 + ty*8 + i;
        long hb = ((long)b*NN + n)*64 + tx*4;
        float v0, v1, v2, v3;
        unpk2(acc2[i][0], v0, v1);
        unpk2(acc2[i][1], v2, v3);
        v0 = sigm(v0 + bv.x); v1 = sigm(v1 + bv.y);
        v2 = sigm(v2 + bv.z); v3 = sigm(v3 + bv.w);
        if (oh == 0) {
            float4 hv = *(const float4*)&g_h[hb];
            *(float4*)&g_zh[hb] = make_float4(v0*hv.x, v1*hv.y, v2*hv.z, v3*hv.w);
        } else {
            *(float4*)&g_r[hb] = make_float4(v0, v1, v2, v3);
        }
    }
}

// ---------------------------------------------------------------------------
// Candidate GEMM (NO=64) + GRU update. tile 64b x 64o, grid (NN, 2).
// ---------------------------------------------------------------------------
template<int CIN>
__global__ void __launch_bounds__(128, 8) cand_k(const float* __restrict__ xext, int t,
                                                 float* __restrict__ curOut,
                                                 float* __restrict__ lastOut) {
    constexpr int KD  = 2*CIN + 2*DOUT;
    constexpr int NKT = (KD + 31) / 32;
    const float* W    = (CIN == 2) ? g_Wu0 : g_Wu1;
    const float* bias = (CIN == 2) ? g_bu0 : g_bu1;

    int n  = blockIdx.x;
    int bh = blockIdx.y;
    int tid = threadIdx.x;
    int tx = tid & 15;
    int ty = tid >> 4;

    __shared__ float As[32][68];
    __shared__ float Ws[32][68];

    unsigned long long acc2[8][2];
#pragma unroll
    for (int i = 0; i < 8; i++) { acc2[i][0] = 0ull; acc2[i][1] = 0ull; }

    for (int kt = 0; kt < NKT; kt++) {
        int k0 = kt * 32;
#pragma unroll
        for (int j = 0; j < 16; j++) {
            int lin = tid + j*128;
            int kl = lin & 31;
            int b  = lin >> 5;
            As[kl][b] = gatherA<CIN,1>(xext, bh*64 + b, n, t, k0 + kl);
        }
#pragma unroll
        for (int j = 0; j < 4; j++) {
            int lin = tid + j*128;
            int c4  = lin & 15;
            int row = lin >> 4;
            int kk = k0 + row;
            float4 v = make_float4(0.f, 0.f, 0.f, 0.f);
            if (kk < KD)
                v = *(const float4*)&W[((long)n*KD + kk)*64 + c4*4];
            *(float4*)&Ws[row][c4*4] = v;
        }
        __syncthreads();
#pragma unroll
        for (int k = 0; k < 32; k++) {
            float4 aLo = *(const float4*)&As[k][ty*8];
            float4 aHi = *(const float4*)&As[k][ty*8 + 4];
            ulonglong2 w2 = *(const ulonglong2*)&Ws[k][tx*4];
            float av[8] = {aLo.x, aLo.y, aLo.z, aLo.w,
                           aHi.x, aHi.y, aHi.z, aHi.w};
#pragma unroll
            for (int i = 0; i < 8; i++) {
                unsigned long long ad = pk2(av[i], av[i]);
                acc2[i][0] = ffma2(ad, w2.x, acc2[i][0]);
                acc2[i][1] = ffma2(ad, w2.y, acc2[i][1]);
            }
        }
        __syncthreads();
    }

    float4 bv = *(const float4*)&bias[n*64 + tx*4];
#pragma unroll
    for (int i = 0; i < 8; i++) {
        int b = bh*64 + ty*8 + i;
        long hb = ((long)b*NN + n)*64 + tx*4;
        float c0, c1, c2, c3;
        unpk2(acc2[i][0], c0, c1);
        unpk2(acc2[i][1], c2, c3);
        c0 = tanhf(c0 + bv.x); c1 = tanhf(c1 + bv.y);
        c2 = tanhf(c2 + bv.z); c3 = tanhf(c3 + bv.w);
        float4 rv = *(const float4*)&g_r[hb];
        float4 hv = *(const float4*)&g_h[hb];
        float4 o;
        o.x = rv.x*hv.x + (1.0f - rv.x)*c0;
        o.y = rv.y*hv.y + (1.0f - rv.y)*c1;
        o.z = rv.z*hv.z + (1.0f - rv.z)*c2;
        o.w = rv.w*hv.w + (1.0f - rv.w)*c3;
        *(float4*)&g_h[hb] = o;
        float* seq = (CIN == 2) ? g_seq0 : curOut;
        *(float4*)&seq[((long)(b*TT + t))*NN*DOUT + (long)n*DOUT + tx*4] = o;
        if (lastOut) *(float4*)&lastOut[hb] = o;
    }
}

// ---------------------------------------------------------------------------
// Host driver — graph-capturable (kernel launches only, default stream)
// ---------------------------------------------------------------------------
extern "C" void kernel_launch(void* const* d_in, const int* in_sizes, int n_in,
                              void* d_out, int out_size) {
    const float* x    = (const float*)d_in[0];
    const float* init = (const float*)d_in[1];
    const float* E    = (const float*)d_in[2];
    const float* adj  = (const float*)d_in[3];
    const float* wg0  = (const float*)d_in[4];
    const float* bg0  = (const float*)d_in[5];
    const float* wu0  = (const float*)d_in[6];
    const float* bu0  = (const float*)d_in[7];
    const float* wg1  = (const float*)d_in[8];
    const float* bg1  = (const float*)d_in[9];
    const float* wu1  = (const float*)d_in[10];
    const float* bu1  = (const float*)d_in[11];

    float* out      = (float*)d_out;
    float* lastBase = out + (long)CURSZ;

    prep_all<<<(unsigned)((C7 + 255) / 256), 256>>>(E, wg0, wu0, wg1, wu1,
                                                    bg0, bu0, bg1, bu1);
    init_h<<<(BND + 255) / 256, 256>>>(init, 0);
    graph_x2_all<<<dim3(5, BT/64), 256>>>(adj, x);

    dim3 gGrid(10, BB/2);            // graph64: 640 blocks x 128 thr

    // ---- layer 0 ----
    for (int t = 0; t < TT; t++) {
        graph64<<<gGrid, 128>>>(adj, 0, t, 0);                        // Gh
        gate_k<2><<<dim3(NN,2,2), 128>>>(x, t);                       // z*h, r
        graph64<<<gGrid, 128>>>(adj, 1, t, 1);                        // Gzh
        cand_k<2><<<dim3(NN,2), 128>>>(x, t, nullptr,
                        (t == TT-1) ? lastBase : nullptr);            // h', seq0
    }
    // ---- layer 1 ----
    init_h<<<(BND + 255) / 256, 256>>>(init, 1);
    graph64<<<dim3(10, BB/2, TT), 128>>>(adj, 2, -1, 2);              // Gx all t
    for (int t = 0; t < TT; t++) {
        graph64<<<gGrid, 128>>>(adj, 0, t, 0);                        // Gh
        gate_k<64><<<dim3(NN,2,2), 128>>>(nullptr, t);
        graph64<<<gGrid, 128>>>(adj, 1, t, 1);                        // Gzh
        cand_k<64><<<dim3(NN,2), 128>>>(nullptr, t, out,
                        (t == TT-1) ? lastBase + BND : nullptr);
    }
}

// round 7
// speedup vs baseline: 1.8153x; 1.3632x over previous
#include <cuda_runtime.h>
#include <math.h>
#include <cstdint>

// Problem constants
#define NN   307
#define TT   12
#define BB   128
#define DIN  2
#define DOUT 64
#define DE   10
#define NNP  320                  // padded node dim for adjT

#define BND   (BB*NN*DOUT)        // 2,514,944
#define CURSZ (BB*TT*NN*DOUT)     // 30,179,328
#define BT    (BB*TT)             // 1536

// ---------------------------------------------------------------------------
// Device scratch
// ---------------------------------------------------------------------------
__device__ float g_Wg0[NN*132*128];
__device__ float g_Wu0[NN*132*64];
__device__ float g_Wg1[NN*256*128];
__device__ float g_Wu1[NN*256*64];
__device__ float g_bg0[NN*128];
__device__ float g_bu0[NN*64];
__device__ float g_bg1[NN*128];
__device__ float g_bu1[NN*64];

__device__ float g_adjT[NNP*NNP];     // adj transposed [m][n], zero-padded

// per-layer state (layer 0 and layer 1 run concurrently on two streams)
__device__ float g_h0  [BND];
__device__ float g_zh0 [BND];
__device__ float g_r0  [BND];
__device__ float g_Gh0 [BND];
__device__ float g_Gzh0[BND];
__device__ float g_h1  [BND];
__device__ float g_zh1 [BND];
__device__ float g_r1  [BND];
__device__ float g_Gh1 [BND];
__device__ float g_Gzh1[BND];
__device__ float g_Gx1 [BND];         // adj @ seq0[t] (layer1, current t)

__device__ float g_Gx2 [BT*NN*DIN];   // adj @ x (layer0, all t) [B,T,N,2]
__device__ float g_seq0[CURSZ];       // layer0 output sequence [B,T,N,64]

__device__ __forceinline__ float sigm(float v) { return 1.0f / (1.0f + expf(-v)); }

// packed fp32x2 helpers (bit-identical fp32 FMA at 2x pipe rate)
__device__ __forceinline__ unsigned long long pk2(float x, float y) {
    unsigned long long r;
    asm("mov.b64 %0, {%1, %2};" : "=l"(r) : "f"(x), "f"(y));
    return r;
}
__device__ __forceinline__ unsigned long long ffma2(unsigned long long a,
                                                    unsigned long long b,
                                                    unsigned long long c) {
    unsigned long long d;
    asm("fma.rn.f32x2 %0, %1, %2, %3;" : "=l"(d) : "l"(a), "l"(b), "l"(c));
    return d;
}
__device__ __forceinline__ void unpk2(unsigned long long v, float& lo, float& hi) {
    asm("mov.b64 {%0, %1}, %2;" : "=f"(lo), "=f"(hi) : "l"(v));
}

// ---------------------------------------------------------------------------
// prep kernels
// ---------------------------------------------------------------------------
#define S_WG0 (132*128)
#define S_WU0 (132*64)
#define S_WG1 (256*128)
#define S_WU1 (256*64)
#define C0 ((long)NN*S_WG0)
#define C1 (C0 + (long)NN*S_WU0)
#define C2 (C1 + (long)NN*S_WG1)
#define C3 (C2 + (long)NN*S_WU1)
#define C4 (C3 + (long)NN*128)
#define C5 (C4 + (long)NN*64)
#define C6 (C5 + (long)NN*128)
#define C7 (C6 + (long)NN*64)

__global__ void prep_all(const float* __restrict__ E,
                         const float* __restrict__ wg0, const float* __restrict__ wu0,
                         const float* __restrict__ wg1, const float* __restrict__ wu1,
                         const float* __restrict__ bg0, const float* __restrict__ bu0,
                         const float* __restrict__ bg1, const float* __restrict__ bu1) {
    long idx = (long)blockIdx.x * blockDim.x + threadIdx.x;
    if (idx >= C7) return;
    const float* pool; float* out; long loc; int S;
    if      (idx < C0) { pool = wg0; out = g_Wg0; loc = idx;      S = S_WG0; }
    else if (idx < C1) { pool = wu0; out = g_Wu0; loc = idx - C0; S = S_WU0; }
    else if (idx < C2) { pool = wg1; out = g_Wg1; loc = idx - C1; S = S_WG1; }
    else if (idx < C3) { pool = wu1; out = g_Wu1; loc = idx - C2; S = S_WU1; }
    else if (idx < C4) { pool = bg0; out = g_bg0; loc = idx - C3; S = 128;   }
    else if (idx < C5) { pool = bu0; out = g_bu0; loc = idx - C4; S = 64;    }
    else if (idx < C6) { pool = bg1; out = g_bg1; loc = idx - C5; S = 128;   }
    else               { pool = bu1; out = g_bu1; loc = idx - C6; S = 64;    }
    int n = (int)(loc / S);
    long j = loc - (long)n * S;
    float acc = 0.0f;
#pragma unroll
    for (int d = 0; d < DE; d++)
        acc += E[n*DE + d] * pool[(long)d*S + j];
    out[loc] = acc;
}

__global__ void prep_adjT(const float* __restrict__ adj) {
    int i = blockIdx.x * blockDim.x + threadIdx.x;
    if (i >= NNP*NNP) return;
    int m = i / NNP, n = i - m*NNP;
    g_adjT[i] = (m < NN && n < NN) ? adj[(long)n*NN + m] : 0.0f;
}

__global__ void init_h(const float* __restrict__ init, int l) {
    int i = blockIdx.x * blockDim.x + threadIdx.x;
    if (i < BND) {
        float v = init[(long)l*BND + i];
        if (l == 0) g_h0[i] = v; else g_h1[i] = v;
    }
}

// ---------------------------------------------------------------------------
// adj @ x for all timesteps (layer0, 2 channels): one launch
// ---------------------------------------------------------------------------
__global__ void __launch_bounds__(256) graph_x2_all(const float* __restrict__ adj,
                                                    const float* __restrict__ x) {
    int n0  = blockIdx.x * 64;
    int bt0 = blockIdx.y * 64;
    int tid = threadIdx.x;
    int tx  = tid & 15;
    int ty  = tid >> 4;

    __shared__ float adjs[32][65];
    __shared__ float xs[64][65];

    float acc[4][4][2] = {};

    for (int m0 = 0; m0 < NN; m0 += 32) {
#pragma unroll
        for (int j = 0; j < 8; j++) {
            int lin = tid + j*256;
            int nl = lin >> 5, ml = lin & 31;
            int n = n0 + nl, m = m0 + ml;
            adjs[ml][nl] = (n < NN && m < NN) ? adj[(long)n*NN + m] : 0.0f;
        }
#pragma unroll
        for (int j = 0; j < 16; j++) {
            int lin = tid + j*256;
            int mc = lin & 63;
            int bt = lin >> 6;
            int m = m0 + (mc >> 1);
            xs[mc][bt] = (m < NN) ? x[((long)(bt0 + bt)*NN + m)*2 + (mc & 1)] : 0.0f;
        }
        __syncthreads();
#pragma unroll
        for (int ml = 0; ml < 32; ml++) {
            float a0 = adjs[ml][ty*4+0];
            float a1 = adjs[ml][ty*4+1];
            float a2 = adjs[ml][ty*4+2];
            float a3 = adjs[ml][ty*4+3];
#pragma unroll
            for (int jj = 0; jj < 4; jj++) {
                float x0 = xs[ml*2+0][tx*4+jj];
                float x1 = xs[ml*2+1][tx*4+jj];
                acc[0][jj][0] += a0*x0; acc[0][jj][1] += a0*x1;
                acc[1][jj][0] += a1*x0; acc[1][jj][1] += a1*x1;
                acc[2][jj][0] += a2*x0; acc[2][jj][1] += a2*x1;
                acc[3][jj][0] += a3*x0; acc[3][jj][1] += a3*x1;
            }
        }
        __syncthreads();
    }
#pragma unroll
    for (int i = 0; i < 4; i++) {
        int n = n0 + ty*4 + i;
        if (n >= NN) continue;
#pragma unroll
        for (int jj = 0; jj < 4; jj++) {
            int bt = bt0 + tx*4 + jj;
            *(float2*)&g_Gx2[((long)bt*NN + n)*2] =
                make_float2(acc[i][jj][0], acc[i][jj][1]);
        }
    }
}

// ---------------------------------------------------------------------------
// Graph propagation, 64 channels. 256 threads, tile 64n x 64c x 1 batch.
// grid (5, 128). Uses pre-transposed padded g_adjT -> fully coalesced,
// conflict-free smem, float4 adj loads in compute.
// srcsel: 0=g_h0, 1=g_zh0, 2=g_seq0[t], 3=g_h1, 4=g_zh1
// dstsel: 0=g_Gh0, 1=g_Gzh0, 2=g_Gx1, 3=g_Gh1, 4=g_Gzh1
// ---------------------------------------------------------------------------
__global__ void __launch_bounds__(256) graph64(int srcsel, int t, int dstsel) {
    const float* src; long sstride;
    switch (srcsel) {
        case 0:  src = g_h0;  sstride = (long)NN*DOUT; break;
        case 1:  src = g_zh0; sstride = (long)NN*DOUT; break;
        case 2:  src = g_seq0 + (long)t*NN*DOUT; sstride = (long)TT*NN*DOUT; break;
        case 3:  src = g_h1;  sstride = (long)NN*DOUT; break;
        default: src = g_zh1; sstride = (long)NN*DOUT; break;
    }
    float* dst;
    switch (dstsel) {
        case 0:  dst = g_Gh0;  break;
        case 1:  dst = g_Gzh0; break;
        case 2:  dst = g_Gx1;  break;
        case 3:  dst = g_Gh1;  break;
        default: dst = g_Gzh1; break;
    }

    int n0 = blockIdx.x * 64;
    int b  = blockIdx.y;
    int tid = threadIdx.x;
    int tx = tid & 15;          // channel group (4 ch)
    int ty = tid >> 4;          // node group   (4 nodes) -> 16 groups = 64 n

    __shared__ float adjs[32][68];     // [m][n], rows 16B-aligned (68*4=272)
    __shared__ float srcs[32][64];     // [m][c]

    unsigned long long acc2[4][2];
#pragma unroll
    for (int i = 0; i < 4; i++) { acc2[i][0] = 0ull; acc2[i][1] = 0ull; }

    const float* sb = src + (long)b * sstride;

    for (int m0 = 0; m0 < NN; m0 += 32) {
        // adjT tile 32m x 64n: 512 float4 / 256 thr = 2 each, coalesced
#pragma unroll
        for (int j = 0; j < 2; j++) {
            int lin = tid + j*256;
            int n4 = lin & 15;
            int ml = lin >> 4;
            float4 v = *(const float4*)&g_adjT[(long)(m0 + ml)*NNP + n0 + n4*4];
            *(float4*)&adjs[ml][n4*4] = v;
        }
        // src tile 32m x 64c: 512 float4 / 256 thr = 2 each
#pragma unroll
        for (int j = 0; j < 2; j++) {
            int lin = tid + j*256;
            int c4 = lin & 15;
            int ml = lin >> 4;
            int m = m0 + ml;
            float4 v = make_float4(0.f, 0.f, 0.f, 0.f);
            if (m < NN) v = *(const float4*)&sb[(long)m*DOUT + c4*4];
            *(float4*)&srcs[ml][c4*4] = v;
        }
        __syncthreads();
#pragma unroll
        for (int ml = 0; ml < 32; ml++) {
            float4 a4 = *(const float4*)&adjs[ml][ty*4];
            ulonglong2 s2 = *(const ulonglong2*)&srcs[ml][tx*4];
            unsigned long long a0 = pk2(a4.x, a4.x);
            unsigned long long a1 = pk2(a4.y, a4.y);
            unsigned long long a2 = pk2(a4.z, a4.z);
            unsigned long long a3 = pk2(a4.w, a4.w);
            acc2[0][0] = ffma2(a0, s2.x, acc2[0][0]);
            acc2[0][1] = ffma2(a0, s2.y, acc2[0][1]);
            acc2[1][0] = ffma2(a1, s2.x, acc2[1][0]);
            acc2[1][1] = ffma2(a1, s2.y, acc2[1][1]);
            acc2[2][0] = ffma2(a2, s2.x, acc2[2][0]);
            acc2[2][1] = ffma2(a2, s2.y, acc2[2][1]);
            acc2[3][0] = ffma2(a3, s2.x, acc2[3][0]);
            acc2[3][1] = ffma2(a3, s2.y, acc2[3][1]);
        }
        __syncthreads();
    }
#pragma unroll
    for (int i = 0; i < 4; i++) {
        int n = n0 + ty*4 + i;
        if (n >= NN) continue;
        float4 v;
        unpk2(acc2[i][0], v.x, v.y);
        unpk2(acc2[i][1], v.z, v.w);
        *(float4*)&dst[((long)b*NN + n)*DOUT + tx*4] = v;
    }
}

// ---------------------------------------------------------------------------
// A-row gather: A[b, kk] = [ x(CIN) | h_or_zh(64) | Gx(CIN) | Gh_or_Gzh(64) ]
// CIN==2 -> layer0 buffers; CIN==64 -> layer1 buffers
// ---------------------------------------------------------------------------
template<int CIN, int MODE>
__device__ __forceinline__ float gatherA(const float* __restrict__ xext,
                                         int b, int n, int t, int kk) {
    long hoff = ((long)b*NN + n)*64;
    if (CIN == 2) {
        if (kk >= 132) return 0.0f;
        long xoff = ((long)b*TT + t)*NN*2 + (long)n*2;
        if (kk < 2)   return xext[xoff + kk];
        if (kk < 66)  return (MODE ? g_zh0 : g_h0)[hoff + (kk - 2)];
        if (kk < 68)  return g_Gx2[xoff + (kk - 66)];
        return (MODE ? g_Gzh0 : g_Gh0)[hoff + (kk - 68)];
    } else {
        long xoff = ((long)b*TT + t)*NN*64 + (long)n*64;
        if (kk < 64)  return g_seq0[xoff + kk];
        if (kk < 128) return (MODE ? g_zh1 : g_h1)[hoff + (kk - 64)];
        if (kk < 192) return g_Gx1[hoff + (kk - 128)];
        return (MODE ? g_Gzh1 : g_Gh1)[hoff + (kk - 192)];
    }
}

// ---------------------------------------------------------------------------
// Gate GEMM: tile 64b x 64o, 128 threads, thread tile 8b x 4o. A as [kk][b].
// grid (NN, 2 bhalf, 2 ohalf).  oh=0: z -> g_zh = z*h.  oh=1: r -> g_r.
// ---------------------------------------------------------------------------
template<int CIN>
__global__ void __launch_bounds__(128, 8) gate_k(const float* __restrict__ xext, int t) {
    constexpr int KD  = 2*CIN + 2*DOUT;         // 132 or 256
    constexpr int NKT = (KD + 31) / 32;         // 5 or 8
    const float* W    = (CIN == 2) ? g_Wg0 : g_Wg1;
    const float* bias = (CIN == 2) ? g_bg0 : g_bg1;
    const float* hbuf = (CIN == 2) ? g_h0  : g_h1;
    float* zhbuf      = (CIN == 2) ? g_zh0 : g_zh1;
    float* rbuf       = (CIN == 2) ? g_r0  : g_r1;

    int n  = blockIdx.x;
    int bh = blockIdx.y;
    int oh = blockIdx.z;
    int tid = threadIdx.x;
    int tx = tid & 15;
    int ty = tid >> 4;

    __shared__ float As[32][68];   // [kk][b]
    __shared__ float Ws[32][68];   // [kk][o]

    unsigned long long acc2[8][2];
#pragma unroll
    for (int i = 0; i < 8; i++) { acc2[i][0] = 0ull; acc2[i][1] = 0ull; }

    for (int kt = 0; kt < NKT; kt++) {
        int k0 = kt * 32;
#pragma unroll
        for (int j = 0; j < 16; j++) {
            int lin = tid + j*128;
            int kl = lin & 31;
            int b  = lin >> 5;
            As[kl][b] = gatherA<CIN,0>(xext, bh*64 + b, n, t, k0 + kl);
        }
#pragma unroll
        for (int j = 0; j < 4; j++) {
            int lin = tid + j*128;
            int c4  = lin & 15;
            int row = lin >> 4;
            int kk = k0 + row;
            float4 v = make_float4(0.f, 0.f, 0.f, 0.f);
            if (kk < KD)
                v = *(const float4*)&W[((long)n*KD + kk)*128 + oh*64 + c4*4];
            *(float4*)&Ws[row][c4*4] = v;
        }
        __syncthreads();
#pragma unroll
        for (int k = 0; k < 32; k++) {
            float4 aLo = *(const float4*)&As[k][ty*8];
            float4 aHi = *(const float4*)&As[k][ty*8 + 4];
            ulonglong2 w2 = *(const ulonglong2*)&Ws[k][tx*4];
            float av[8] = {aLo.x, aLo.y, aLo.z, aLo.w,
                           aHi.x, aHi.y, aHi.z, aHi.w};
#pragma unroll
            for (int i = 0; i < 8; i++) {
                unsigned long long ad = pk2(av[i], av[i]);
                acc2[i][0] = ffma2(ad, w2.x, acc2[i][0]);
                acc2[i][1] = ffma2(ad, w2.y, acc2[i][1]);
            }
        }
        __syncthreads();
    }

    float4 bv = *(const float4*)&bias[n*128 + oh*64 + tx*4];
#pragma unroll
    for (int i = 0; i < 8; i++) {
        int b = bh*64 + ty*8 + i;
        long hb = ((long)b*NN + n)*64 + tx*4;
        float v0, v1, v2, v3;
        unpk2(acc2[i][0], v0, v1);
        unpk2(acc2[i][1], v2, v3);
        v0 = sigm(v0 + bv.x); v1 = sigm(v1 + bv.y);
        v2 = sigm(v2 + bv.z); v3 = sigm(v3 + bv.w);
        if (oh == 0) {
            float4 hv = *(const float4*)&hbuf[hb];
            *(float4*)&zhbuf[hb] = make_float4(v0*hv.x, v1*hv.y, v2*hv.z, v3*hv.w);
        } else {
            *(float4*)&rbuf[hb] = make_float4(v0, v1, v2, v3);
        }
    }
}

// ---------------------------------------------------------------------------
// Candidate GEMM (NO=64) + GRU update. tile 64b x 64o, grid (NN, 2).
// ---------------------------------------------------------------------------
template<int CIN>
__global__ void __launch_bounds__(128, 8) cand_k(const float* __restrict__ xext, int t,
                                                 float* __restrict__ curOut,
                                                 float* __restrict__ lastOut) {
    constexpr int KD  = 2*CIN + 2*DOUT;
    constexpr int NKT = (KD + 31) / 32;
    const float* W    = (CIN == 2) ? g_Wu0 : g_Wu1;
    const float* bias = (CIN == 2) ? g_bu0 : g_bu1;
    float* hbuf       = (CIN == 2) ? g_h0  : g_h1;
    const float* rbuf = (CIN == 2) ? g_r0  : g_r1;

    int n  = blockIdx.x;
    int bh = blockIdx.y;
    int tid = threadIdx.x;
    int tx = tid & 15;
    int ty = tid >> 4;

    __shared__ float As[32][68];
    __shared__ float Ws[32][68];

    unsigned long long acc2[8][2];
#pragma unroll
    for (int i = 0; i < 8; i++) { acc2[i][0] = 0ull; acc2[i][1] = 0ull; }

    for (int kt = 0; kt < NKT; kt++) {
        int k0 = kt * 32;
#pragma unroll
        for (int j = 0; j < 16; j++) {
            int lin = tid + j*128;
            int kl = lin & 31;
            int b  = lin >> 5;
            As[kl][b] = gatherA<CIN,1>(xext, bh*64 + b, n, t, k0 + kl);
        }
#pragma unroll
        for (int j = 0; j < 4; j++) {
            int lin = tid + j*128;
            int c4  = lin & 15;
            int row = lin >> 4;
            int kk = k0 + row;
            float4 v = make_float4(0.f, 0.f, 0.f, 0.f);
            if (kk < KD)
                v = *(const float4*)&W[((long)n*KD + kk)*64 + c4*4];
            *(float4*)&Ws[row][c4*4] = v;
        }
        __syncthreads();
#pragma unroll
        for (int k = 0; k < 32; k++) {
            float4 aLo = *(const float4*)&As[k][ty*8];
            float4 aHi = *(const float4*)&As[k][ty*8 + 4];
            ulonglong2 w2 = *(const ulonglong2*)&Ws[k][tx*4];
            float av[8] = {aLo.x, aLo.y, aLo.z, aLo.w,
                           aHi.x, aHi.y, aHi.z, aHi.w};
#pragma unroll
            for (int i = 0; i < 8; i++) {
                unsigned long long ad = pk2(av[i], av[i]);
                acc2[i][0] = ffma2(ad, w2.x, acc2[i][0]);
                acc2[i][1] = ffma2(ad, w2.y, acc2[i][1]);
            }
        }
        __syncthreads();
    }

    float4 bv = *(const float4*)&bias[n*64 + tx*4];
#pragma unroll
    for (int i = 0; i < 8; i++) {
        int b = bh*64 + ty*8 + i;
        long hb = ((long)b*NN + n)*64 + tx*4;
        float c0, c1, c2, c3;
        unpk2(acc2[i][0], c0, c1);
        unpk2(acc2[i][1], c2, c3);
        c0 = tanhf(c0 + bv.x); c1 = tanhf(c1 + bv.y);
        c2 = tanhf(c2 + bv.z); c3 = tanhf(c3 + bv.w);
        float4 rv = *(const float4*)&rbuf[hb];
        float4 hv = *(const float4*)&hbuf[hb];
        float4 o;
        o.x = rv.x*hv.x + (1.0f - rv.x)*c0;
        o.y = rv.y*hv.y + (1.0f - rv.y)*c1;
        o.z = rv.z*hv.z + (1.0f - rv.z)*c2;
        o.w = rv.w*hv.w + (1.0f - rv.w)*c3;
        *(float4*)&hbuf[hb] = o;
        float* seq = (CIN == 2) ? g_seq0 : curOut;
        *(float4*)&seq[((long)(b*TT + t))*NN*DOUT + (long)n*DOUT + tx*4] = o;
        if (lastOut) *(float4*)&lastOut[hb] = o;
    }
}

// ---------------------------------------------------------------------------
// Host driver — graph-capturable. Two streams: layer0 on sA, layer1 on sB,
// joined per-t via events (fork/join capture pattern).
// ---------------------------------------------------------------------------
extern "C" void kernel_launch(void* const* d_in, const int* in_sizes, int n_in,
                              void* d_out, int out_size) {
    const float* x    = (const float*)d_in[0];
    const float* init = (const float*)d_in[1];
    const float* E    = (const float*)d_in[2];
    const float* adj  = (const float*)d_in[3];
    const float* wg0  = (const float*)d_in[4];
    const float* bg0  = (const float*)d_in[5];
    const float* wu0  = (const float*)d_in[6];
    const float* bu0  = (const float*)d_in[7];
    const float* wg1  = (const float*)d_in[8];
    const float* bg1  = (const float*)d_in[9];
    const float* wu1  = (const float*)d_in[10];
    const float* bu1  = (const float*)d_in[11];

    float* out      = (float*)d_out;
    float* lastBase = out + (long)CURSZ;

    // persistent streams/events (host resources, no device memory)
    static cudaStream_t sA = nullptr, sB = nullptr;
    static cudaEvent_t eFork = nullptr, eA = nullptr, eB = nullptr, e0[TT];
    if (!sA) {
        cudaStreamCreateWithFlags(&sA, cudaStreamNonBlocking);
        cudaStreamCreateWithFlags(&sB, cudaStreamNonBlocking);
        cudaEventCreateWithFlags(&eFork, cudaEventDisableTiming);
        cudaEventCreateWithFlags(&eA, cudaEventDisableTiming);
        cudaEventCreateWithFlags(&eB, cudaEventDisableTiming);
        for (int t = 0; t < TT; t++)
            cudaEventCreateWithFlags(&e0[t], cudaEventDisableTiming);
    }

    // ---- prelude on the capture (default) stream ----
    prep_all<<<(unsigned)((C7 + 255) / 256), 256>>>(E, wg0, wu0, wg1, wu1,
                                                    bg0, bu0, bg1, bu1);
    prep_adjT<<<(NNP*NNP + 255) / 256, 256>>>(adj);
    init_h<<<(BND + 255) / 256, 256>>>(init, 0);
    init_h<<<(BND + 255) / 256, 256>>>(init, 1);
    graph_x2_all<<<dim3(5, BT/64), 256>>>(adj, x);

    // fork
    cudaEventRecord(eFork, 0);
    cudaStreamWaitEvent(sA, eFork, 0);
    cudaStreamWaitEvent(sB, eFork, 0);

    dim3 gGrid(5, BB);

    // ---- layer 0 on sA ----
    for (int t = 0; t < TT; t++) {
        graph64<<<gGrid, 256, 0, sA>>>(0, t, 0);                        // Gh0
        gate_k<2><<<dim3(NN,2,2), 128, 0, sA>>>(x, t);                  // z*h, r
        graph64<<<gGrid, 256, 0, sA>>>(1, t, 1);                        // Gzh0
        cand_k<2><<<dim3(NN,2), 128, 0, sA>>>(x, t, nullptr,
                        (t == TT-1) ? lastBase : nullptr);              // h0', seq0[t]
        cudaEventRecord(e0[t], sA);
    }
    // ---- layer 1 on sB (step t gated on seq0[t]) ----
    for (int t = 0; t < TT; t++) {
        cudaStreamWaitEvent(sB, e0[t], 0);
        graph64<<<gGrid, 256, 0, sB>>>(2, t, 2);                        // Gx1 = adj@seq0[t]
        graph64<<<gGrid, 256, 0, sB>>>(3, t, 3);                        // Gh1
        gate_k<64><<<dim3(NN,2,2), 128, 0, sB>>>(nullptr, t);
        graph64<<<gGrid, 256, 0, sB>>>(4, t, 4);                        // Gzh1
        cand_k<64><<<dim3(NN,2), 128, 0, sB>>>(nullptr, t, out,
                        (t == TT-1) ? lastBase + BND : nullptr);
    }

    // join back into the capture stream
    cudaEventRecord(eA, sA);
    cudaEventRecord(eB, sB);
    cudaStreamWaitEvent(0, eA, 0);
    cudaStreamWaitEvent(0, eB, 0);
}

// round 8
// speedup vs baseline: 1.8621x; 1.0258x over previous
#include <cuda_runtime.h>
#include <cuda_bf16.h>
#include <math.h>
#include <cstdint>

// Problem constants
#define NN   307
#define TT   12
#define BB   128
#define DIN  2
#define DOUT 64
#define DE   10
#define NNP  320                  // padded node dim (k-dim for mma, mult of 16)

#define BND   (BB*NN*DOUT)        // 2,514,944
#define CURSZ (BB*TT*NN*DOUT)     // 30,179,328
#define BT    (BB*TT)             // 1536

// ---------------------------------------------------------------------------
// Device scratch
// ---------------------------------------------------------------------------
__device__ float g_Wg0[NN*132*128];
__device__ float g_Wu0[NN*132*64];
__device__ float g_Wg1[NN*256*128];
__device__ float g_Wu1[NN*256*64];
__device__ float g_bg0[NN*128];
__device__ float g_bu0[NN*64];
__device__ float g_bg1[NN*128];
__device__ float g_bu1[NN*64];

__device__ __nv_bfloat16 g_adjH[NNP*NNP];   // adj [n][m] bf16 hi plane, zero-padded
__device__ __nv_bfloat16 g_adjL[NNP*NNP];   // adj [n][m] bf16 lo plane

// per-layer state (layer 0 and layer 1 run concurrently on two streams)
__device__ float g_h0  [BND];
__device__ float g_zh0 [BND];
__device__ float g_r0  [BND];
__device__ float g_Gh0 [BND];
__device__ float g_Gzh0[BND];
__device__ float g_h1  [BND];
__device__ float g_zh1 [BND];
__device__ float g_r1  [BND];
__device__ float g_Gh1 [BND];
__device__ float g_Gzh1[BND];
__device__ float g_Gx1 [BND];         // adj @ seq0[t] (layer1, current t)

__device__ float g_Gx2 [BT*NN*DIN];   // adj @ x (layer0, all t) [B,T,N,2]
__device__ float g_seq0[CURSZ];       // layer0 output sequence [B,T,N,64]

__device__ __forceinline__ float sigm(float v) { return 1.0f / (1.0f + expf(-v)); }

// packed fp32x2 helpers (for the GEMMs, unchanged)
__device__ __forceinline__ unsigned long long pk2(float x, float y) {
    unsigned long long r;
    asm("mov.b64 %0, {%1, %2};" : "=l"(r) : "f"(x), "f"(y));
    return r;
}
__device__ __forceinline__ unsigned long long ffma2(unsigned long long a,
                                                    unsigned long long b,
                                                    unsigned long long c) {
    unsigned long long d;
    asm("fma.rn.f32x2 %0, %1, %2, %3;" : "=l"(d) : "l"(a), "l"(b), "l"(c));
    return d;
}
__device__ __forceinline__ void unpk2(unsigned long long v, float& lo, float& hi) {
    asm("mov.b64 {%0, %1}, %2;" : "=f"(lo), "=f"(hi) : "l"(v));
}

// bf16 mma.sync m16n8k16 (legacy tensor path, compiles for compute_100)
__device__ __forceinline__ void mma_bf16(float* c, const uint32_t* a,
                                         uint32_t b0, uint32_t b1) {
    asm volatile(
        "mma.sync.aligned.m16n8k16.row.col.f32.bf16.bf16.f32 "
        "{%0,%1,%2,%3}, {%4,%5,%6,%7}, {%8,%9}, {%0,%1,%2,%3};"
        : "+f"(c[0]), "+f"(c[1]), "+f"(c[2]), "+f"(c[3])
        : "r"(a[0]), "r"(a[1]), "r"(a[2]), "r"(a[3]), "r"(b0), "r"(b1));
}

// ---------------------------------------------------------------------------
// prep kernels
// ---------------------------------------------------------------------------
#define S_WG0 (132*128)
#define S_WU0 (132*64)
#define S_WG1 (256*128)
#define S_WU1 (256*64)
#define C0 ((long)NN*S_WG0)
#define C1 (C0 + (long)NN*S_WU0)
#define C2 (C1 + (long)NN*S_WG1)
#define C3 (C2 + (long)NN*S_WU1)
#define C4 (C3 + (long)NN*128)
#define C5 (C4 + (long)NN*64)
#define C6 (C5 + (long)NN*128)
#define C7 (C6 + (long)NN*64)

__global__ void prep_all(const float* __restrict__ E,
                         const float* __restrict__ wg0, const float* __restrict__ wu0,
                         const float* __restrict__ wg1, const float* __restrict__ wu1,
                         const float* __restrict__ bg0, const float* __restrict__ bu0,
                         const float* __restrict__ bg1, const float* __restrict__ bu1) {
    long idx = (long)blockIdx.x * blockDim.x + threadIdx.x;
    if (idx >= C7) return;
    const float* pool; float* out; long loc; int S;
    if      (idx < C0) { pool = wg0; out = g_Wg0; loc = idx;      S = S_WG0; }
    else if (idx < C1) { pool = wu0; out = g_Wu0; loc = idx - C0; S = S_WU0; }
    else if (idx < C2) { pool = wg1; out = g_Wg1; loc = idx - C1; S = S_WG1; }
    else if (idx < C3) { pool = wu1; out = g_Wu1; loc = idx - C2; S = S_WU1; }
    else if (idx < C4) { pool = bg0; out = g_bg0; loc = idx - C3; S = 128;   }
    else if (idx < C5) { pool = bu0; out = g_bu0; loc = idx - C4; S = 64;    }
    else if (idx < C6) { pool = bg1; out = g_bg1; loc = idx - C5; S = 128;   }
    else               { pool = bu1; out = g_bu1; loc = idx - C6; S = 64;    }
    int n = (int)(loc / S);
    long j = loc - (long)n * S;
    float acc = 0.0f;
#pragma unroll
    for (int d = 0; d < DE; d++)
        acc += E[n*DE + d] * pool[(long)d*S + j];
    out[loc] = acc;
}

// adj -> bf16 hi/lo planes, [n][m] layout, zero-padded to 320x320
__global__ void prep_adjB(const float* __restrict__ adj) {
    int i = blockIdx.x * blockDim.x + threadIdx.x;
    if (i >= NNP*NNP) return;
    int n = i / NNP, m = i - n*NNP;
    float v = (n < NN && m < NN) ? adj[(long)n*NN + m] : 0.0f;
    __nv_bfloat16 h = __float2bfloat16(v);
    __nv_bfloat16 l = __float2bfloat16(v - __bfloat162float(h));
    g_adjH[i] = h;
    g_adjL[i] = l;
}

__global__ void init_h(const float* __restrict__ init, int l) {
    int i = blockIdx.x * blockDim.x + threadIdx.x;
    if (i < BND) {
        float v = init[(long)l*BND + i];
        if (l == 0) g_h0[i] = v; else g_h1[i] = v;
    }
}

// ---------------------------------------------------------------------------
// adj @ x for all timesteps (layer0, 2 channels): one launch, f32 (tiny)
// ---------------------------------------------------------------------------
__global__ void __launch_bounds__(256) graph_x2_all(const float* __restrict__ adj,
                                                    const float* __restrict__ x) {
    int n0  = blockIdx.x * 64;
    int bt0 = blockIdx.y * 64;
    int tid = threadIdx.x;
    int tx  = tid & 15;
    int ty  = tid >> 4;

    __shared__ float adjs[32][65];
    __shared__ float xs[64][65];

    float acc[4][4][2] = {};

    for (int m0 = 0; m0 < NN; m0 += 32) {
#pragma unroll
        for (int j = 0; j < 8; j++) {
            int lin = tid + j*256;
            int nl = lin >> 5, ml = lin & 31;
            int n = n0 + nl, m = m0 + ml;
            adjs[ml][nl] = (n < NN && m < NN) ? adj[(long)n*NN + m] : 0.0f;
        }
#pragma unroll
        for (int j = 0; j < 16; j++) {
            int lin = tid + j*256;
            int mc = lin & 63;
            int bt = lin >> 6;
            int m = m0 + (mc >> 1);
            xs[mc][bt] = (m < NN) ? x[((long)(bt0 + bt)*NN + m)*2 + (mc & 1)] : 0.0f;
        }
        __syncthreads();
#pragma unroll
        for (int ml = 0; ml < 32; ml++) {
            float a0 = adjs[ml][ty*4+0];
            float a1 = adjs[ml][ty*4+1];
            float a2 = adjs[ml][ty*4+2];
            float a3 = adjs[ml][ty*4+3];
#pragma unroll
            for (int jj = 0; jj < 4; jj++) {
                float x0 = xs[ml*2+0][tx*4+jj];
                float x1 = xs[ml*2+1][tx*4+jj];
                acc[0][jj][0] += a0*x0; acc[0][jj][1] += a0*x1;
                acc[1][jj][0] += a1*x0; acc[1][jj][1] += a1*x1;
                acc[2][jj][0] += a2*x0; acc[2][jj][1] += a2*x1;
                acc[3][jj][0] += a3*x0; acc[3][jj][1] += a3*x1;
            }
        }
        __syncthreads();
    }
#pragma unroll
    for (int i = 0; i < 4; i++) {
        int n = n0 + ty*4 + i;
        if (n >= NN) continue;
#pragma unroll
        for (int jj = 0; jj < 4; jj++) {
            int bt = bt0 + tx*4 + jj;
            *(float2*)&g_Gx2[((long)bt*NN + n)*2] =
                make_float2(acc[i][jj][0], acc[i][jj][1]);
        }
    }
}

// ---------------------------------------------------------------------------
// Graph propagation via bf16 split mma.sync (3 passes: AhBh + AhBl + AlBh).
// Per block: 64 nodes x 64 channels x 1 batch; 8 warps as 4(m16) x 2(n32).
// grid (5, 128).  K loop: 20 x k16 over padded 320 m-dim.
// srcsel: 0=g_h0, 1=g_zh0, 2=g_seq0[t], 3=g_h1, 4=g_zh1
// dstsel: 0=g_Gh0, 1=g_Gzh0, 2=g_Gx1, 3=g_Gh1, 4=g_Gzh1
// ---------------------------------------------------------------------------
__global__ void __launch_bounds__(256) graph64_mma(int srcsel, int t, int dstsel) {
    const float* src; long sstride;
    switch (srcsel) {
        case 0:  src = g_h0;  sstride = (long)NN*DOUT; break;
        case 1:  src = g_zh0; sstride = (long)NN*DOUT; break;
        case 2:  src = g_seq0 + (long)t*NN*DOUT; sstride = (long)TT*NN*DOUT; break;
        case 3:  src = g_h1;  sstride = (long)NN*DOUT; break;
        default: src = g_zh1; sstride = (long)NN*DOUT; break;
    }
    float* dst;
    switch (dstsel) {
        case 0:  dst = g_Gh0;  break;
        case 1:  dst = g_Gzh0; break;
        case 2:  dst = g_Gx1;  break;
        case 3:  dst = g_Gh1;  break;
        default: dst = g_Gzh1; break;
    }

    int n0  = blockIdx.x * 64;
    int b   = blockIdx.y;
    int tid = threadIdx.x;
    int lane = tid & 31;
    int wid  = tid >> 5;
    int wm = wid & 3;            // m16 tile: rows n0 + wm*16
    int wn = wid >> 2;           // n32 tile: cols wn*32

    // [row][k] tiles, rows padded to 20 halves (40B) for store-conflict relief
    __shared__ __nv_bfloat16 Ah[64][20], Al[64][20];   // A: [n][m16]
    __shared__ __nv_bfloat16 Bh[64][20], Bl[64][20];   // B: [c][m16]

    float acc[4][4];             // [n8 tile][frag reg]
#pragma unroll
    for (int i = 0; i < 4; i++)
#pragma unroll
        for (int j = 0; j < 4; j++) acc[i][j] = 0.0f;

    const float* sb = src + (long)b * sstride;
    int bc = tid & 63;           // B fill: channel
    int bm = (tid >> 6) * 4;     // B fill: first of 4 k rows

    for (int m0 = 0; m0 < NNP; m0 += 16) {
        // A fill: 64n x 16k bf16 x2 planes from pre-split gmem (u32 = 2 bf16)
#pragma unroll
        for (int j = 0; j < 2; j++) {
            int lin = tid + j*256;
            int nl = lin >> 3, kp = lin & 7;
            long src_off = (long)(n0 + nl)*NNP + m0 + kp*2;
            *(uint32_t*)&Ah[nl][kp*2] = *(const uint32_t*)&g_adjH[src_off];
            *(uint32_t*)&Al[nl][kp*2] = *(const uint32_t*)&g_adjL[src_off];
        }
        // B fill: 16k x 64c from f32 src, split into hi/lo
#pragma unroll
        for (int i = 0; i < 4; i++) {
            int ml = bm + i;
            int m  = m0 + ml;
            float v = (m < NN) ? sb[(long)m*DOUT + bc] : 0.0f;
            __nv_bfloat16 h = __float2bfloat16(v);
            __nv_bfloat16 l = __float2bfloat16(v - __bfloat162float(h));
            Bh[bc][ml] = h;
            Bl[bc][ml] = l;
        }
        __syncthreads();

        // A frags (m16k16): reg j: row = wm*16 + lane/4 + (j&1)*8,
        //                   kpair = (lane&3)*2 + (j&2)*4
        uint32_t a_h[4], a_l[4];
#pragma unroll
        for (int j = 0; j < 4; j++) {
            int row = wm*16 + (lane >> 2) + (j & 1)*8;
            int kp  = (lane & 3)*2 + (j & 2)*4;
            a_h[j] = *(const uint32_t*)&Ah[row][kp];
            a_l[j] = *(const uint32_t*)&Al[row][kp];
        }
        // B frags + mma per n8 tile
#pragma unroll
        for (int tn = 0; tn < 4; tn++) {
            int cc  = wn*32 + tn*8 + (lane >> 2);
            int k0p = (lane & 3)*2;
            uint32_t b_h0 = *(const uint32_t*)&Bh[cc][k0p];
            uint32_t b_h1 = *(const uint32_t*)&Bh[cc][k0p + 8];
            uint32_t b_l0 = *(const uint32_t*)&Bl[cc][k0p];
            uint32_t b_l1 = *(const uint32_t*)&Bl[cc][k0p + 8];
            mma_bf16(acc[tn], a_h, b_h0, b_h1);
            mma_bf16(acc[tn], a_h, b_l0, b_l1);
            mma_bf16(acc[tn], a_l, b_h0, b_h1);
        }
        __syncthreads();
    }

    // Epilogue: C frag -> dst[b][n][c]
    long db = (long)b * NN * DOUT;
#pragma unroll
    for (int tn = 0; tn < 4; tn++) {
        int n = n0 + wm*16 + (lane >> 2);
        int c = wn*32 + tn*8 + (lane & 3)*2;
        if (n < NN)
            *(float2*)&dst[db + (long)n*DOUT + c] =
                make_float2(acc[tn][0], acc[tn][1]);
        if (n + 8 < NN)
            *(float2*)&dst[db + (long)(n + 8)*DOUT + c] =
                make_float2(acc[tn][2], acc[tn][3]);
    }
}

// ---------------------------------------------------------------------------
// A-row gather: A[b, kk] = [ x(CIN) | h_or_zh(64) | Gx(CIN) | Gh_or_Gzh(64) ]
// ---------------------------------------------------------------------------
template<int CIN, int MODE>
__device__ __forceinline__ float gatherA(const float* __restrict__ xext,
                                         int b, int n, int t, int kk) {
    long hoff = ((long)b*NN + n)*64;
    if (CIN == 2) {
        if (kk >= 132) return 0.0f;
        long xoff = ((long)b*TT + t)*NN*2 + (long)n*2;
        if (kk < 2)   return xext[xoff + kk];
        if (kk < 66)  return (MODE ? g_zh0 : g_h0)[hoff + (kk - 2)];
        if (kk < 68)  return g_Gx2[xoff + (kk - 66)];
        return (MODE ? g_Gzh0 : g_Gh0)[hoff + (kk - 68)];
    } else {
        long xoff = ((long)b*TT + t)*NN*64 + (long)n*64;
        if (kk < 64)  return g_seq0[xoff + kk];
        if (kk < 128) return (MODE ? g_zh1 : g_h1)[hoff + (kk - 64)];
        if (kk < 192) return g_Gx1[hoff + (kk - 128)];
        return (MODE ? g_Gzh1 : g_Gh1)[hoff + (kk - 192)];
    }
}

// ---------------------------------------------------------------------------
// Gate GEMM: tile 64b x 64o, 128 threads, thread tile 8b x 4o. A as [kk][b].
// ---------------------------------------------------------------------------
template<int CIN>
__global__ void __launch_bounds__(128, 8) gate_k(const float* __restrict__ xext, int t) {
    constexpr int KD  = 2*CIN + 2*DOUT;
    constexpr int NKT = (KD + 31) / 32;
    const float* W    = (CIN == 2) ? g_Wg0 : g_Wg1;
    const float* bias = (CIN == 2) ? g_bg0 : g_bg1;
    const float* hbuf = (CIN == 2) ? g_h0  : g_h1;
    float* zhbuf      = (CIN == 2) ? g_zh0 : g_zh1;
    float* rbuf       = (CIN == 2) ? g_r0  : g_r1;

    int n  = blockIdx.x;
    int bh = blockIdx.y;
    int oh = blockIdx.z;
    int tid = threadIdx.x;
    int tx = tid & 15;
    int ty = tid >> 4;

    __shared__ float As[32][68];
    __shared__ float Ws[32][68];

    unsigned long long acc2[8][2];
#pragma unroll
    for (int i = 0; i < 8; i++) { acc2[i][0] = 0ull; acc2[i][1] = 0ull; }

    for (int kt = 0; kt < NKT; kt++) {
        int k0 = kt * 32;
#pragma unroll
        for (int j = 0; j < 16; j++) {
            int lin = tid + j*128;
            int kl = lin & 31;
            int b  = lin >> 5;
            As[kl][b] = gatherA<CIN,0>(xext, bh*64 + b, n, t, k0 + kl);
        }
#pragma unroll
        for (int j = 0; j < 4; j++) {
            int lin = tid + j*128;
            int c4  = lin & 15;
            int row = lin >> 4;
            int kk = k0 + row;
            float4 v = make_float4(0.f, 0.f, 0.f, 0.f);
            if (kk < KD)
                v = *(const float4*)&W[((long)n*KD + kk)*128 + oh*64 + c4*4];
            *(float4*)&Ws[row][c4*4] = v;
        }
        __syncthreads();
#pragma unroll
        for (int k = 0; k < 32; k++) {
            float4 aLo = *(const float4*)&As[k][ty*8];
            float4 aHi = *(const float4*)&As[k][ty*8 + 4];
            ulonglong2 w2 = *(const ulonglong2*)&Ws[k][tx*4];
            float av[8] = {aLo.x, aLo.y, aLo.z, aLo.w,
                           aHi.x, aHi.y, aHi.z, aHi.w};
#pragma unroll
            for (int i = 0; i < 8; i++) {
                unsigned long long ad = pk2(av[i], av[i]);
                acc2[i][0] = ffma2(ad, w2.x, acc2[i][0]);
                acc2[i][1] = ffma2(ad, w2.y, acc2[i][1]);
            }
        }
        __syncthreads();
    }

    float4 bv = *(const float4*)&bias[n*128 + oh*64 + tx*4];
#pragma unroll
    for (int i = 0; i < 8; i++) {
        int b = bh*64 + ty*8 + i;
        long hb = ((long)b*NN + n)*64 + tx*4;
        float v0, v1, v2, v3;
        unpk2(acc2[i][0], v0, v1);
        unpk2(acc2[i][1], v2, v3);
        v0 = sigm(v0 + bv.x); v1 = sigm(v1 + bv.y);
        v2 = sigm(v2 + bv.z); v3 = sigm(v3 + bv.w);
        if (oh == 0) {
            float4 hv = *(const float4*)&hbuf[hb];
            *(float4*)&zhbuf[hb] = make_float4(v0*hv.x, v1*hv.y, v2*hv.z, v3*hv.w);
        } else {
            *(float4*)&rbuf[hb] = make_float4(v0, v1, v2, v3);
        }
    }
}

// ---------------------------------------------------------------------------
// Candidate GEMM (NO=64) + GRU update. tile 64b x 64o, grid (NN, 2).
// ---------------------------------------------------------------------------
template<int CIN>
__global__ void __launch_bounds__(128, 8) cand_k(const float* __restrict__ xext, int t,
                                                 float* __restrict__ curOut,
                                                 float* __restrict__ lastOut) {
    constexpr int KD  = 2*CIN + 2*DOUT;
    constexpr int NKT = (KD + 31) / 32;
    const float* W    = (CIN == 2) ? g_Wu0 : g_Wu1;
    const float* bias = (CIN == 2) ? g_bu0 : g_bu1;
    float* hbuf       = (CIN == 2) ? g_h0  : g_h1;
    const float* rbuf = (CIN == 2) ? g_r0  : g_r1;

    int n  = blockIdx.x;
    int bh = blockIdx.y;
    int tid = threadIdx.x;
    int tx = tid & 15;
    int ty = tid >> 4;

    __shared__ float As[32][68];
    __shared__ float Ws[32][68];

    unsigned long long acc2[8][2];
#pragma unroll
    for (int i = 0; i < 8; i++) { acc2[i][0] = 0ull; acc2[i][1] = 0ull; }

    for (int kt = 0; kt < NKT; kt++) {
        int k0 = kt * 32;
#pragma unroll
        for (int j = 0; j < 16; j++) {
            int lin = tid + j*128;
            int kl = lin & 31;
            int b  = lin >> 5;
            As[kl][b] = gatherA<CIN,1>(xext, bh*64 + b, n, t, k0 + kl);
        }
#pragma unroll
        for (int j = 0; j < 4; j++) {
            int lin = tid + j*128;
            int c4  = lin & 15;
            int row = lin >> 4;
            int kk = k0 + row;
            float4 v = make_float4(0.f, 0.f, 0.f, 0.f);
            if (kk < KD)
                v = *(const float4*)&W[((long)n*KD + kk)*64 + c4*4];
            *(float4*)&Ws[row][c4*4] = v;
        }
        __syncthreads();
#pragma unroll
        for (int k = 0; k < 32; k++) {
            float4 aLo = *(const float4*)&As[k][ty*8];
            float4 aHi = *(const float4*)&As[k][ty*8 + 4];
            ulonglong2 w2 = *(const ulonglong2*)&Ws[k][tx*4];
            float av[8] = {aLo.x, aLo.y, aLo.z, aLo.w,
                           aHi.x, aHi.y, aHi.z, aHi.w};
#pragma unroll
            for (int i = 0; i < 8; i++) {
                unsigned long long ad = pk2(av[i], av[i]);
                acc2[i][0] = ffma2(ad, w2.x, acc2[i][0]);
                acc2[i][1] = ffma2(ad, w2.y, acc2[i][1]);
            }
        }
        __syncthreads();
    }

    float4 bv = *(const float4*)&bias[n*64 + tx*4];
#pragma unroll
    for (int i = 0; i < 8; i++) {
        int b = bh*64 + ty*8 + i;
        long hb = ((long)b*NN + n)*64 + tx*4;
        float c0, c1, c2, c3;
        unpk2(acc2[i][0], c0, c1);
        unpk2(acc2[i][1], c2, c3);
        c0 = tanhf(c0 + bv.x); c1 = tanhf(c1 + bv.y);
        c2 = tanhf(c2 + bv.z); c3 = tanhf(c3 + bv.w);
        float4 rv = *(const float4*)&rbuf[hb];
        float4 hv = *(const float4*)&hbuf[hb];
        float4 o;
        o.x = rv.x*hv.x + (1.0f - rv.x)*c0;
        o.y = rv.y*hv.y + (1.0f - rv.y)*c1;
        o.z = rv.z*hv.z + (1.0f - rv.z)*c2;
        o.w = rv.w*hv.w + (1.0f - rv.w)*c3;
        *(float4*)&hbuf[hb] = o;
        float* seq = (CIN == 2) ? g_seq0 : curOut;
        *(float4*)&seq[((long)(b*TT + t))*NN*DOUT + (long)n*DOUT + tx*4] = o;
        if (lastOut) *(float4*)&lastOut[hb] = o;
    }
}

// ---------------------------------------------------------------------------
// Host driver — graph-capturable. Two streams: layer0 on sA, layer1 on sB.
// ---------------------------------------------------------------------------
extern "C" void kernel_launch(void* const* d_in, const int* in_sizes, int n_in,
                              void* d_out, int out_size) {
    const float* x    = (const float*)d_in[0];
    const float* init = (const float*)d_in[1];
    const float* E    = (const float*)d_in[2];
    const float* adj  = (const float*)d_in[3];
    const float* wg0  = (const float*)d_in[4];
    const float* bg0  = (const float*)d_in[5];
    const float* wu0  = (const float*)d_in[6];
    const float* bu0  = (const float*)d_in[7];
    const float* wg1  = (const float*)d_in[8];
    const float* bg1  = (const float*)d_in[9];
    const float* wu1  = (const float*)d_in[10];
    const float* bu1  = (const float*)d_in[11];

    float* out      = (float*)d_out;
    float* lastBase = out + (long)CURSZ;

    static cudaStream_t sA = nullptr, sB = nullptr;
    static cudaEvent_t eFork = nullptr, eA = nullptr, eB = nullptr, e0[TT];
    if (!sA) {
        cudaStreamCreateWithFlags(&sA, cudaStreamNonBlocking);
        cudaStreamCreateWithFlags(&sB, cudaStreamNonBlocking);
        cudaEventCreateWithFlags(&eFork, cudaEventDisableTiming);
        cudaEventCreateWithFlags(&eA, cudaEventDisableTiming);
        cudaEventCreateWithFlags(&eB, cudaEventDisableTiming);
        for (int t = 0; t < TT; t++)
            cudaEventCreateWithFlags(&e0[t], cudaEventDisableTiming);
    }

    // ---- prelude on the capture (default) stream ----
    prep_all<<<(unsigned)((C7 + 255) / 256), 256>>>(E, wg0, wu0, wg1, wu1,
                                                    bg0, bu0, bg1, bu1);
    prep_adjB<<<(NNP*NNP + 255) / 256, 256>>>(adj);
    init_h<<<(BND + 255) / 256, 256>>>(init, 0);
    init_h<<<(BND + 255) / 256, 256>>>(init, 1);
    graph_x2_all<<<dim3(5, BT/64), 256>>>(adj, x);

    cudaEventRecord(eFork, 0);
    cudaStreamWaitEvent(sA, eFork, 0);
    cudaStreamWaitEvent(sB, eFork, 0);

    dim3 gGrid(5, BB);

    // ---- layer 0 on sA ----
    for (int t = 0; t < TT; t++) {
        graph64_mma<<<gGrid, 256, 0, sA>>>(0, t, 0);                    // Gh0
        gate_k<2><<<dim3(NN,2,2), 128, 0, sA>>>(x, t);                  // z*h, r
        graph64_mma<<<gGrid, 256, 0, sA>>>(1, t, 1);                    // Gzh0
        cand_k<2><<<dim3(NN,2), 128, 0, sA>>>(x, t, nullptr,
                        (t == TT-1) ? lastBase : nullptr);              // h0', seq0[t]
        cudaEventRecord(e0[t], sA);
    }
    // ---- layer 1 on sB (step t gated on seq0[t]) ----
    for (int t = 0; t < TT; t++) {
        cudaStreamWaitEvent(sB, e0[t], 0);
        graph64_mma<<<gGrid, 256, 0, sB>>>(2, t, 2);                    // Gx1
        graph64_mma<<<gGrid, 256, 0, sB>>>(3, t, 3);                    // Gh1
        gate_k<64><<<dim3(NN,2,2), 128, 0, sB>>>(nullptr, t);
        graph64_mma<<<gGrid, 256, 0, sB>>>(4, t, 4);                    // Gzh1
        cand_k<64><<<dim3(NN,2), 128, 0, sB>>>(nullptr, t, out,
                        (t == TT-1) ? lastBase + BND : nullptr);
    }

    cudaEventRecord(eA, sA);
    cudaEventRecord(eB, sB);
    cudaStreamWaitEvent(0, eA, 0);
    cudaStreamWaitEvent(0, eB, 0);
}